// round 6
// baseline (speedup 1.0000x reference)
#include <cuda_runtime.h>
#include <cstdint>

#define D_MODEL 1024
#define N_HEADS 16
#define D_K     64
#define BATCH   2
#define SEQ     2048
#define M_ROWS  (BATCH * SEQ)   // 4096

// Scratch (allocation-free rule: __device__ globals). tf32 payloads as u32 bits.
__device__ uint32_t t_q [M_ROWS * D_MODEL];   // packed-32 acts (also reused for packed O)
__device__ uint32_t t_k [M_ROWS * D_MODEL];
__device__ uint32_t t_v [M_ROWS * D_MODEL];
__device__ uint32_t t_wq[D_MODEL * D_MODEL];  // transposed + packed-32 weights
__device__ uint32_t t_wk[D_MODEL * D_MODEL];
__device__ uint32_t t_wv[D_MODEL * D_MODEL];
__device__ uint32_t t_wo[D_MODEL * D_MODEL];
__device__ uint32_t g_Q [M_ROWS * D_MODEL];   // natural [token][1024], pre-scaled tf32
__device__ uint32_t g_K [M_ROWS * D_MODEL];   // natural tf32
__device__ uint32_t g_V [M_ROWS * D_MODEL];   // natural tf32
__device__ uint32_t g_O [M_ROWS * D_MODEL];   // natural tf32 (attn out)

__device__ __forceinline__ uint32_t f2tf32(float x) {
    uint32_t r;
    asm("cvt.rna.tf32.f32 %0, %1;" : "=r"(r) : "f"(x));
    return r;
}

__device__ __forceinline__ void mma_tf32(float c[4],
                                         uint32_t a0, uint32_t a1, uint32_t a2, uint32_t a3,
                                         uint32_t b0, uint32_t b1) {
    asm volatile(
        "mma.sync.aligned.m16n8k8.row.col.f32.tf32.tf32.f32 "
        "{%0,%1,%2,%3}, {%4,%5,%6,%7}, {%8,%9}, {%0,%1,%2,%3};"
        : "+f"(c[0]), "+f"(c[1]), "+f"(c[2]), "+f"(c[3])
        : "r"(a0), "r"(a1), "r"(a2), "r"(a3), "r"(b0), "r"(b1));
}

__device__ __forceinline__ uint32_t smem_u32(const void* p) {
    return (uint32_t)__cvta_generic_to_shared(p);
}
__device__ __forceinline__ void cpasync16(uint32_t dst, const void* src) {
    asm volatile("cp.async.cg.shared.global [%0], [%1], 16;" :: "r"(dst), "l"(src));
}
__device__ __forceinline__ void cpasync_commit() {
    asm volatile("cp.async.commit_group;");
}
template<int N> __device__ __forceinline__ void cpasync_wait() {
    asm volatile("cp.async.wait_group %0;" :: "n"(N));
}

// pack within a 32-k group: logical kk -> phys u32 position (GEMM frag order)
// kk = c8*8 + tg + sel*4  ->  phys = tg*8 + c8*2 + sel
__device__ __forceinline__ int phys32(int kk) {
    return (kk & 3) * 8 + ((kk >> 3) & 3) * 2 + ((kk >> 2) & 1);
}

// ---------------------------------------------------------------------------
// Pre-pass 1: pack activations: fp32 [rows][1024] -> tf32 packed-32.
// ---------------------------------------------------------------------------
__global__ __launch_bounds__(256)
void pack_act_kernel(const float* __restrict__ in, uint32_t* __restrict__ out, int n)
{
    int i = blockIdx.x * 256 + threadIdx.x;
    if (i < n) {
        int row = i >> 10, col = i & 1023;
        out[(size_t)row * 1024 + (col & ~31) + phys32(col & 31)] = f2tf32(in[i]);
    }
}

// Pre-pass 1b: permute-only (input already tf32 bits)
__global__ __launch_bounds__(256)
void pack_u32_kernel(const uint32_t* __restrict__ in, uint32_t* __restrict__ out, int n)
{
    int i = blockIdx.x * 256 + threadIdx.x;
    if (i < n) {
        int row = i >> 10, col = i & 1023;
        out[(size_t)row * 1024 + (col & ~31) + phys32(col & 31)] = in[i];
    }
}

// ---------------------------------------------------------------------------
// Pre-pass 2: transpose + pack weights: W[k][n] fp32 -> Wt[n][k packed-32] tf32.
// Block (32,8), grid (32,32). smem tile 32x33.
// ---------------------------------------------------------------------------
__global__ __launch_bounds__(256)
void pack_wT_kernel(const float* __restrict__ W, uint32_t* __restrict__ Wt)
{
    __shared__ float ts[32][33];
    int k0 = blockIdx.x * 32, n0 = blockIdx.y * 32;
    int tx = threadIdx.x, ty = threadIdx.y;
    #pragma unroll
    for (int r = 0; r < 4; r++)
        ts[ty + r * 8][tx] = W[(size_t)(k0 + ty + r * 8) * 1024 + n0 + tx];
    __syncthreads();
    #pragma unroll
    for (int r = 0; r < 4; r++) {
        int n = ty + r * 8;
        Wt[(size_t)(n0 + n) * 1024 + k0 + phys32(tx)] = f2tf32(ts[tx][n]);
    }
}

// ---------------------------------------------------------------------------
// TF32 GEMM, packed operands. C = alpha*(A@W + bias).
// A: packed-32 [m][1024]; Wt: packed-32 transposed [n][1024].
// BM=BN=128, BK=32, 2-stage cp.async, 256 thr, warp tile 64x32, pitch 36.
// All fragment loads are LDS.128. OUT: 0=fp32 natural, 1=tf32 natural.
// ---------------------------------------------------------------------------
#define GP 36
#define GSA (128 * GP)
#define GSB (128 * GP)
#define GEMM_SMEM ((2 * (GSA + GSB)) * 4)

template<int OUT>
__global__ __launch_bounds__(256)
void gemm_tf32(const uint32_t* __restrict__ A,
               const uint32_t* __restrict__ Wt,
               const float* __restrict__ bias,
               void* __restrict__ Cout,
               float alpha)
{
    extern __shared__ uint32_t sg[];
    uint32_t* Asm = sg;                 // [2][128][GP]
    uint32_t* Bsm = sg + 2 * GSA;       // [2][128][GP]

    const int tid  = threadIdx.x;
    const int lane = tid & 31;
    const int gid  = lane >> 2;
    const int tg   = lane & 3;
    const int wid  = tid >> 5;
    const int warp_m = wid & 1;
    const int warp_n = wid >> 1;
    const int m0 = blockIdx.y * 128;
    const int n0 = blockIdx.x * 128;

    float c[4][4][4];
    #pragma unroll
    for (int mt = 0; mt < 4; mt++)
        #pragma unroll
        for (int nt = 0; nt < 4; nt++)
            #pragma unroll
            for (int i = 0; i < 4; i++) c[mt][nt][i] = 0.f;

    // Prologue stage 0
    #pragma unroll
    for (int i = 0; i < 4; i++) {
        int idx = tid + i * 256;
        int row = idx >> 3, ch = idx & 7;
        cpasync16(smem_u32(&Asm[row * GP + ch * 4]),
                  &A[(size_t)(m0 + row) * 1024 + ch * 4]);
    }
    #pragma unroll
    for (int i = 0; i < 4; i++) {
        int idx = tid + i * 256;
        int row = idx >> 3, ch = idx & 7;
        cpasync16(smem_u32(&Bsm[row * GP + ch * 4]),
                  &Wt[(size_t)(n0 + row) * 1024 + ch * 4]);
    }
    cpasync_commit();

    int st = 0;
    for (int k0 = 0; k0 < D_MODEL; k0 += 32) {
        cpasync_wait<0>();
        __syncthreads();

        if (k0 + 32 < D_MODEL) {
            uint32_t* Ad = Asm + (st ^ 1) * GSA;
            uint32_t* Bd = Bsm + (st ^ 1) * GSB;
            #pragma unroll
            for (int i = 0; i < 4; i++) {
                int idx = tid + i * 256;
                int row = idx >> 3, ch = idx & 7;
                cpasync16(smem_u32(&Ad[row * GP + ch * 4]),
                          &A[(size_t)(m0 + row) * 1024 + k0 + 32 + ch * 4]);
            }
            #pragma unroll
            for (int i = 0; i < 4; i++) {
                int idx = tid + i * 256;
                int row = idx >> 3, ch = idx & 7;
                cpasync16(smem_u32(&Bd[row * GP + ch * 4]),
                          &Wt[(size_t)(n0 + row) * 1024 + k0 + 32 + ch * 4]);
            }
            cpasync_commit();
        }

        const uint32_t* As = Asm + st * GSA;
        const uint32_t* Bs = Bsm + st * GSB;

        #pragma unroll
        for (int cp = 0; cp < 2; cp++) {
            uint4 aL[4], aH[4], bF[4];
            #pragma unroll
            for (int mt = 0; mt < 4; mt++) {
                int r = warp_m * 64 + mt * 16;
                aL[mt] = *(const uint4*)&As[(r + gid    ) * GP + tg * 8 + cp * 4];
                aH[mt] = *(const uint4*)&As[(r + gid + 8) * GP + tg * 8 + cp * 4];
            }
            #pragma unroll
            for (int nt = 0; nt < 4; nt++)
                bF[nt] = *(const uint4*)&Bs[(warp_n * 32 + nt * 8 + gid) * GP + tg * 8 + cp * 4];
            #pragma unroll
            for (int mt = 0; mt < 4; mt++)
                #pragma unroll
                for (int nt = 0; nt < 4; nt++)
                    mma_tf32(c[mt][nt], aL[mt].x, aH[mt].x, aL[mt].y, aH[mt].y,
                             bF[nt].x, bF[nt].y);
            #pragma unroll
            for (int mt = 0; mt < 4; mt++)
                #pragma unroll
                for (int nt = 0; nt < 4; nt++)
                    mma_tf32(c[mt][nt], aL[mt].z, aH[mt].z, aL[mt].w, aH[mt].w,
                             bF[nt].z, bF[nt].w);
        }
        st ^= 1;
    }

    #pragma unroll
    for (int mt = 0; mt < 4; mt++) {
        int r0 = m0 + warp_m * 64 + mt * 16 + gid;
        #pragma unroll
        for (int nt = 0; nt < 4; nt++) {
            int col = n0 + warp_n * 32 + nt * 8 + tg * 2;
            float2 bb = *(const float2*)&bias[col];
            float v00 = alpha * (c[mt][nt][0] + bb.x);
            float v01 = alpha * (c[mt][nt][1] + bb.y);
            float v10 = alpha * (c[mt][nt][2] + bb.x);
            float v11 = alpha * (c[mt][nt][3] + bb.y);
            if (OUT == 0) {
                float* C = (float*)Cout;
                *(float2*)&C[(size_t)r0 * 1024 + col] = make_float2(v00, v01);
                *(float2*)&C[(size_t)(r0 + 8) * 1024 + col] = make_float2(v10, v11);
            } else {
                uint32_t* C = (uint32_t*)Cout;
                uint2 u0 = { f2tf32(v00), f2tf32(v01) };
                *(uint2*)&C[(size_t)r0 * 1024 + col] = u0;
                uint2 u1 = { f2tf32(v10), f2tf32(v11) };
                *(uint2*)&C[(size_t)(r0 + 8) * 1024 + col] = u1;
            }
        }
    }
}

// ---------------------------------------------------------------------------
// TF32 flash attention — byte-identical to the round-4 passing version.
// CTA = 128 q rows x one (b,h). 8 warps x 16 rows. Q pre-scaled tf32 in regs;
// K/V natural tf32 via 2-stage cp.async. P via smem (tf32). Writes natural
// tf32 to g_O. smem = 106496 B.
// ---------------------------------------------------------------------------
#define KS_P 68
#define VS_P 72
#define PS_P 68
#define K_STAGE (64 * KS_P)
#define V_STAGE (64 * VS_P)
#define ATTN_SMEM ((2 * K_STAGE + 2 * V_STAGE + 128 * PS_P) * 4)

__global__ __launch_bounds__(256)
void attn_tf32(const uint32_t* __restrict__ Q,
               const uint32_t* __restrict__ K,
               const uint32_t* __restrict__ V,
               uint32_t* __restrict__ O)
{
    extern __shared__ uint32_t sa[];
    uint32_t* Kbuf = sa;                         // [2][64][KS_P] tf32
    uint32_t* Vbuf = sa + 2 * K_STAGE;           // [2][64][VS_P] tf32
    uint32_t* Ps   = sa + 2 * K_STAGE + 2 * V_STAGE;  // [128][PS_P] tf32

    const int tid  = threadIdx.x;
    const int lane = tid & 31;
    const int wid  = tid >> 5;
    const int gid  = lane >> 2;
    const int tg   = lane & 3;
    const int row_base = wid * 16;

    const int q0 = blockIdx.x * 128;
    const int h  = blockIdx.y;
    const int b  = blockIdx.z;

    const uint32_t* Qb = Q + (size_t)b * SEQ * D_MODEL + h * D_K;
    const uint32_t* Kb = K + (size_t)b * SEQ * D_MODEL + h * D_K;
    const uint32_t* Vb = V + (size_t)b * SEQ * D_MODEL + h * D_K;

    uint32_t qf[8][4];
    {
        const uint32_t* qr0 = Qb + (size_t)(q0 + row_base + gid) * D_MODEL;
        const uint32_t* qr1 = qr0 + (size_t)8 * D_MODEL;
        #pragma unroll
        for (int c8 = 0; c8 < 8; c8++) {
            qf[c8][0] = qr0[c8 * 8 + tg    ];
            qf[c8][1] = qr1[c8 * 8 + tg    ];
            qf[c8][2] = qr0[c8 * 8 + tg + 4];
            qf[c8][3] = qr1[c8 * 8 + tg + 4];
        }
    }

    #pragma unroll
    for (int i = 0; i < 4; i++) {
        int idx = tid + i * 256;
        int r = idx >> 4, c4 = (idx & 15) * 4;
        cpasync16(smem_u32(&Kbuf[r * KS_P + c4]), &Kb[(size_t)r * D_MODEL + c4]);
        cpasync16(smem_u32(&Vbuf[r * VS_P + c4]), &Vb[(size_t)r * D_MODEL + c4]);
    }
    cpasync_commit();

    float o[8][4];
    #pragma unroll
    for (int nt = 0; nt < 8; nt++)
        #pragma unroll
        for (int i = 0; i < 4; i++) o[nt][i] = 0.f;
    float m_i[2] = { -1e30f, -1e30f };
    float l_i[2] = { 0.f, 0.f };

    int st = 0;
    for (int kt = 0; kt < SEQ; kt += 64) {
        cpasync_wait<0>();
        __syncthreads();

        if (kt + 64 < SEQ) {
            uint32_t* Kd = Kbuf + (st ^ 1) * K_STAGE;
            uint32_t* Vd = Vbuf + (st ^ 1) * V_STAGE;
            #pragma unroll
            for (int i = 0; i < 4; i++) {
                int idx = tid + i * 256;
                int r = idx >> 4, c4 = (idx & 15) * 4;
                cpasync16(smem_u32(&Kd[r * KS_P + c4]),
                          &Kb[(size_t)(kt + 64 + r) * D_MODEL + c4]);
                cpasync16(smem_u32(&Vd[r * VS_P + c4]),
                          &Vb[(size_t)(kt + 64 + r) * D_MODEL + c4]);
            }
            cpasync_commit();
        }

        const uint32_t* Ks = Kbuf + st * K_STAGE;
        const uint32_t* Vs = Vbuf + st * V_STAGE;

        float s[8][4];
        #pragma unroll
        for (int nt = 0; nt < 8; nt++)
            #pragma unroll
            for (int i = 0; i < 4; i++) s[nt][i] = 0.f;

        #pragma unroll
        for (int c8 = 0; c8 < 8; c8++) {
            int ks = c8 * 8;
            #pragma unroll
            for (int nt = 0; nt < 8; nt++) {
                uint32_t b0 = Ks[(nt * 8 + gid) * KS_P + ks + tg];
                uint32_t b1 = Ks[(nt * 8 + gid) * KS_P + ks + tg + 4];
                mma_tf32(s[nt], qf[c8][0], qf[c8][1], qf[c8][2], qf[c8][3], b0, b1);
            }
        }

        #pragma unroll
        for (int half = 0; half < 2; half++) {
            float mx = -1e30f;
            #pragma unroll
            for (int nt = 0; nt < 8; nt++)
                mx = fmaxf(mx, fmaxf(s[nt][half * 2], s[nt][half * 2 + 1]));
            mx = fmaxf(mx, __shfl_xor_sync(0xffffffffu, mx, 1));
            mx = fmaxf(mx, __shfl_xor_sync(0xffffffffu, mx, 2));

            float mnew = fmaxf(m_i[half], mx);
            float corr = __expf(m_i[half] - mnew);
            float rs = 0.f;
            #pragma unroll
            for (int nt = 0; nt < 8; nt++) {
                s[nt][half * 2]     = __expf(s[nt][half * 2]     - mnew);
                s[nt][half * 2 + 1] = __expf(s[nt][half * 2 + 1] - mnew);
                rs += s[nt][half * 2] + s[nt][half * 2 + 1];
            }
            rs += __shfl_xor_sync(0xffffffffu, rs, 1);
            rs += __shfl_xor_sync(0xffffffffu, rs, 2);

            l_i[half] = l_i[half] * corr + rs;
            m_i[half] = mnew;
            #pragma unroll
            for (int nt = 0; nt < 8; nt++) {
                o[nt][half * 2]     *= corr;
                o[nt][half * 2 + 1] *= corr;
            }
        }

        __syncwarp();
        #pragma unroll
        for (int nt = 0; nt < 8; nt++) {
            int cc = nt * 8 + tg * 2;
            Ps[(row_base + gid    ) * PS_P + cc    ] = f2tf32(s[nt][0]);
            Ps[(row_base + gid    ) * PS_P + cc + 1] = f2tf32(s[nt][1]);
            Ps[(row_base + gid + 8) * PS_P + cc    ] = f2tf32(s[nt][2]);
            Ps[(row_base + gid + 8) * PS_P + cc + 1] = f2tf32(s[nt][3]);
        }
        __syncwarp();

        #pragma unroll
        for (int c8 = 0; c8 < 8; c8++) {
            int ks = c8 * 8;
            uint32_t a0 = Ps[(row_base + gid    ) * PS_P + ks + tg];
            uint32_t a1 = Ps[(row_base + gid + 8) * PS_P + ks + tg];
            uint32_t a2 = Ps[(row_base + gid    ) * PS_P + ks + tg + 4];
            uint32_t a3 = Ps[(row_base + gid + 8) * PS_P + ks + tg + 4];
            #pragma unroll
            for (int nt = 0; nt < 8; nt++) {
                uint32_t b0 = Vs[(ks + tg    ) * VS_P + nt * 8 + gid];
                uint32_t b1 = Vs[(ks + tg + 4) * VS_P + nt * 8 + gid];
                mma_tf32(o[nt], a0, a1, a2, a3, b0, b1);
            }
        }
        st ^= 1;
    }

    float inv0 = 1.0f / l_i[0];
    float inv1 = 1.0f / l_i[1];
    uint32_t* Ob = O + (size_t)b * SEQ * D_MODEL + h * D_K;
    int r0 = q0 + row_base + gid;
    #pragma unroll
    for (int nt = 0; nt < 8; nt++) {
        int col = nt * 8 + tg * 2;
        uint2 t0 = { f2tf32(o[nt][0] * inv0), f2tf32(o[nt][1] * inv0) };
        *(uint2*)&Ob[(size_t)r0 * D_MODEL + col] = t0;
        uint2 t1 = { f2tf32(o[nt][2] * inv1), f2tf32(o[nt][3] * inv1) };
        *(uint2*)&Ob[(size_t)(r0 + 8) * D_MODEL + col] = t1;
    }
}

// ---------------------------------------------------------------------------
// kernel_launch — inputs: q, k, v, w_q, b_q, w_k, b_k, w_v, b_v, w_o, b_o
// ---------------------------------------------------------------------------
extern "C" void kernel_launch(void* const* d_in, const int* in_sizes, int n_in,
                              void* d_out, int out_size)
{
    const float* q   = (const float*)d_in[0];
    const float* k   = (const float*)d_in[1];
    const float* v   = (const float*)d_in[2];
    const float* w_q = (const float*)d_in[3];
    const float* b_q = (const float*)d_in[4];
    const float* w_k = (const float*)d_in[5];
    const float* b_k = (const float*)d_in[6];
    const float* w_v = (const float*)d_in[7];
    const float* b_v = (const float*)d_in[8];
    const float* w_o = (const float*)d_in[9];
    const float* b_o = (const float*)d_in[10];
    float* out = (float*)d_out;

    uint32_t *tq, *tk, *tv, *twq, *twk, *twv, *two, *gq, *gk, *gv, *go;
    cudaGetSymbolAddress((void**)&tq,  t_q);
    cudaGetSymbolAddress((void**)&tk,  t_k);
    cudaGetSymbolAddress((void**)&tv,  t_v);
    cudaGetSymbolAddress((void**)&twq, t_wq);
    cudaGetSymbolAddress((void**)&twk, t_wk);
    cudaGetSymbolAddress((void**)&twv, t_wv);
    cudaGetSymbolAddress((void**)&two, t_wo);
    cudaGetSymbolAddress((void**)&gq,  g_Q);
    cudaGetSymbolAddress((void**)&gk,  g_K);
    cudaGetSymbolAddress((void**)&gv,  g_V);
    cudaGetSymbolAddress((void**)&go,  g_O);

    cudaFuncSetAttribute(gemm_tf32<0>, cudaFuncAttributeMaxDynamicSharedMemorySize, GEMM_SMEM);
    cudaFuncSetAttribute(gemm_tf32<1>, cudaFuncAttributeMaxDynamicSharedMemorySize, GEMM_SMEM);
    cudaFuncSetAttribute(attn_tf32,    cudaFuncAttributeMaxDynamicSharedMemorySize, ATTN_SMEM);

    // Pre-pass: pack activations; transpose+pack weights
    const int n_act = M_ROWS * D_MODEL;
    pack_act_kernel<<<n_act / 256, 256>>>(q, tq, n_act);
    pack_act_kernel<<<n_act / 256, 256>>>(k, tk, n_act);
    pack_act_kernel<<<n_act / 256, 256>>>(v, tv, n_act);
    dim3 wt_grid(32, 32), wt_block(32, 8);
    pack_wT_kernel<<<wt_grid, wt_block>>>(w_q, twq);
    pack_wT_kernel<<<wt_grid, wt_block>>>(w_k, twk);
    pack_wT_kernel<<<wt_grid, wt_block>>>(w_v, twv);
    pack_wT_kernel<<<wt_grid, wt_block>>>(w_o, two);

    dim3 gemm_grid(D_MODEL / 128, M_ROWS / 128);  // (8, 32)
    gemm_tf32<1><<<gemm_grid, 256, GEMM_SMEM>>>(tq, twq, b_q, gq, 0.125f);
    gemm_tf32<1><<<gemm_grid, 256, GEMM_SMEM>>>(tk, twk, b_k, gk, 1.0f);
    gemm_tf32<1><<<gemm_grid, 256, GEMM_SMEM>>>(tv, twv, b_v, gv, 1.0f);

    dim3 attn_grid(SEQ / 128, N_HEADS, BATCH);    // (16, 16, 2)
    attn_tf32<<<attn_grid, 256, ATTN_SMEM>>>(gq, gk, gv, go);

    // Pack attention output (already tf32 bits) for the packed final GEMM.
    // t_q is dead after the Q projection — reuse it.
    pack_u32_kernel<<<n_act / 256, 256>>>(go, tq, n_act);

    gemm_tf32<0><<<gemm_grid, 256, GEMM_SMEM>>>(tq, two, b_o, out, 1.0f);
}

// round 8
// speedup vs baseline: 1.1324x; 1.1324x over previous
#include <cuda_runtime.h>
#include <cstdint>

#define D_MODEL 1024
#define N_HEADS 16
#define D_K     64
#define BATCH   2
#define SEQ     2048
#define M_ROWS  (BATCH * SEQ)   // 4096

// Scratch (allocation-free rule: __device__ globals). tf32 payloads as u32 bits.
__device__ uint32_t t_q [M_ROWS * D_MODEL];   // packed-32 acts
__device__ uint32_t t_k [M_ROWS * D_MODEL];
__device__ uint32_t t_v [M_ROWS * D_MODEL];
__device__ uint32_t t_wq[D_MODEL * D_MODEL];  // transposed + packed-32 weights
__device__ uint32_t t_wk[D_MODEL * D_MODEL];
__device__ uint32_t t_wv[D_MODEL * D_MODEL];
__device__ uint32_t t_wo[D_MODEL * D_MODEL];
__device__ uint32_t g_Q [M_ROWS * D_MODEL];   // natural [token][1024], pre-scaled tf32
__device__ uint32_t g_K [M_ROWS * D_MODEL];   // natural tf32
__device__ uint32_t g_V [M_ROWS * D_MODEL];   // natural tf32
__device__ uint32_t g_O [M_ROWS * D_MODEL];   // packed-32 tf32 (attn out, GEMM A layout)

__device__ __forceinline__ uint32_t f2tf32(float x) {
    uint32_t r;
    asm("cvt.rna.tf32.f32 %0, %1;" : "=r"(r) : "f"(x));
    return r;
}

__device__ __forceinline__ void mma_tf32(float c[4],
                                         uint32_t a0, uint32_t a1, uint32_t a2, uint32_t a3,
                                         uint32_t b0, uint32_t b1) {
    asm volatile(
        "mma.sync.aligned.m16n8k8.row.col.f32.tf32.tf32.f32 "
        "{%0,%1,%2,%3}, {%4,%5,%6,%7}, {%8,%9}, {%0,%1,%2,%3};"
        : "+f"(c[0]), "+f"(c[1]), "+f"(c[2]), "+f"(c[3])
        : "r"(a0), "r"(a1), "r"(a2), "r"(a3), "r"(b0), "r"(b1));
}

__device__ __forceinline__ uint32_t smem_u32(const void* p) {
    return (uint32_t)__cvta_generic_to_shared(p);
}
__device__ __forceinline__ void cpasync16(uint32_t dst, const void* src) {
    asm volatile("cp.async.cg.shared.global [%0], [%1], 16;" :: "r"(dst), "l"(src));
}
__device__ __forceinline__ void cpasync_commit() {
    asm volatile("cp.async.commit_group;");
}
template<int N> __device__ __forceinline__ void cpasync_wait() {
    asm volatile("cp.async.wait_group %0;" :: "n"(N));
}

// pack within a 32-k group: logical kk -> phys u32 position (GEMM frag order)
// kk = c8*8 + tg + sel*4  ->  phys = tg*8 + c8*2 + sel
__device__ __forceinline__ int phys32(int kk) {
    return (kk & 3) * 8 + ((kk >> 3) & 3) * 2 + ((kk >> 2) & 1);
}

// ---------------------------------------------------------------------------
// Pre-pass 1: pack q/k/v activations in ONE launch (blockIdx.y selects array).
// fp32 [rows][1024] -> tf32 packed-32.
// ---------------------------------------------------------------------------
__global__ __launch_bounds__(256)
void pack_act3_kernel(const float* __restrict__ q, const float* __restrict__ k,
                      const float* __restrict__ v,
                      uint32_t* __restrict__ tq, uint32_t* __restrict__ tk,
                      uint32_t* __restrict__ tv, int n)
{
    int i = blockIdx.x * 256 + threadIdx.x;
    if (i >= n) return;
    const float* in = (blockIdx.y == 0) ? q : (blockIdx.y == 1) ? k : v;
    uint32_t*   out = (blockIdx.y == 0) ? tq : (blockIdx.y == 1) ? tk : tv;
    int row = i >> 10, col = i & 1023;
    out[(size_t)row * 1024 + (col & ~31) + phys32(col & 31)] = f2tf32(in[i]);
}

// ---------------------------------------------------------------------------
// Pre-pass 2: transpose + pack all 4 weights in ONE launch (blockIdx.z selects).
// W[k][n] fp32 -> Wt[n][k packed-32] tf32.
// ---------------------------------------------------------------------------
__global__ __launch_bounds__(256)
void pack_wT4_kernel(const float* __restrict__ wq, const float* __restrict__ wk,
                     const float* __restrict__ wv, const float* __restrict__ wo,
                     uint32_t* __restrict__ twq, uint32_t* __restrict__ twk,
                     uint32_t* __restrict__ twv, uint32_t* __restrict__ two)
{
    __shared__ float ts[32][33];
    const float* W  = (blockIdx.z == 0) ? wq  : (blockIdx.z == 1) ? wk  :
                      (blockIdx.z == 2) ? wv  : wo;
    uint32_t*    Wt = (blockIdx.z == 0) ? twq : (blockIdx.z == 1) ? twk :
                      (blockIdx.z == 2) ? twv : two;
    int k0 = blockIdx.x * 32, n0 = blockIdx.y * 32;
    int tx = threadIdx.x, ty = threadIdx.y;
    #pragma unroll
    for (int r = 0; r < 4; r++)
        ts[ty + r * 8][tx] = W[(size_t)(k0 + ty + r * 8) * 1024 + n0 + tx];
    __syncthreads();
    #pragma unroll
    for (int r = 0; r < 4; r++) {
        int n = ty + r * 8;
        Wt[(size_t)(n0 + n) * 1024 + k0 + phys32(tx)] = f2tf32(ts[tx][n]);
    }
}

// ---------------------------------------------------------------------------
// TF32 GEMM, packed operands. C = alpha*(A@W + bias).
// A: packed-32 [m][1024]; Wt: packed-32 transposed [n][1024].
// BM=BN=128, BK=32, 2-stage cp.async, 256 thr, warp tile 64x32, pitch 36.
// Forced 2 CTAs/SM; B frags reused across mt, A frags consumed immediately.
// OUT: 0=fp32 natural, 1=tf32 natural.
// ---------------------------------------------------------------------------
#define GP 36
#define GSA (128 * GP)
#define GSB (128 * GP)
#define GEMM_SMEM ((2 * (GSA + GSB)) * 4)

template<int OUT>
__global__ __launch_bounds__(256, 2)
void gemm_tf32(const uint32_t* __restrict__ A,
               const uint32_t* __restrict__ Wt,
               const float* __restrict__ bias,
               void* __restrict__ Cout,
               float alpha)
{
    extern __shared__ uint32_t sg[];
    uint32_t* Asm = sg;                 // [2][128][GP]
    uint32_t* Bsm = sg + 2 * GSA;       // [2][128][GP]

    const int tid  = threadIdx.x;
    const int lane = tid & 31;
    const int gid  = lane >> 2;
    const int tg   = lane & 3;
    const int wid  = tid >> 5;
    const int warp_m = wid & 1;
    const int warp_n = wid >> 1;
    const int m0 = blockIdx.y * 128;
    const int n0 = blockIdx.x * 128;

    float c[4][4][4];
    #pragma unroll
    for (int mt = 0; mt < 4; mt++)
        #pragma unroll
        for (int nt = 0; nt < 4; nt++)
            #pragma unroll
            for (int i = 0; i < 4; i++) c[mt][nt][i] = 0.f;

    // Prologue stage 0
    #pragma unroll
    for (int i = 0; i < 4; i++) {
        int idx = tid + i * 256;
        int row = idx >> 3, ch = idx & 7;
        cpasync16(smem_u32(&Asm[row * GP + ch * 4]),
                  &A[(size_t)(m0 + row) * 1024 + ch * 4]);
    }
    #pragma unroll
    for (int i = 0; i < 4; i++) {
        int idx = tid + i * 256;
        int row = idx >> 3, ch = idx & 7;
        cpasync16(smem_u32(&Bsm[row * GP + ch * 4]),
                  &Wt[(size_t)(n0 + row) * 1024 + ch * 4]);
    }
    cpasync_commit();

    int st = 0;
    for (int k0 = 0; k0 < D_MODEL; k0 += 32) {
        cpasync_wait<0>();
        __syncthreads();

        if (k0 + 32 < D_MODEL) {
            uint32_t* Ad = Asm + (st ^ 1) * GSA;
            uint32_t* Bd = Bsm + (st ^ 1) * GSB;
            #pragma unroll
            for (int i = 0; i < 4; i++) {
                int idx = tid + i * 256;
                int row = idx >> 3, ch = idx & 7;
                cpasync16(smem_u32(&Ad[row * GP + ch * 4]),
                          &A[(size_t)(m0 + row) * 1024 + k0 + 32 + ch * 4]);
            }
            #pragma unroll
            for (int i = 0; i < 4; i++) {
                int idx = tid + i * 256;
                int row = idx >> 3, ch = idx & 7;
                cpasync16(smem_u32(&Bd[row * GP + ch * 4]),
                          &Wt[(size_t)(n0 + row) * 1024 + k0 + 32 + ch * 4]);
            }
            cpasync_commit();
        }

        const uint32_t* As = Asm + st * GSA;
        const uint32_t* Bs = Bsm + st * GSB;

        #pragma unroll
        for (int cp = 0; cp < 2; cp++) {
            uint4 bF[4];
            #pragma unroll
            for (int nt = 0; nt < 4; nt++)
                bF[nt] = *(const uint4*)&Bs[(warp_n * 32 + nt * 8 + gid) * GP + tg * 8 + cp * 4];
            #pragma unroll
            for (int mt = 0; mt < 4; mt++) {
                int r = warp_m * 64 + mt * 16;
                uint4 aL = *(const uint4*)&As[(r + gid    ) * GP + tg * 8 + cp * 4];
                uint4 aH = *(const uint4*)&As[(r + gid + 8) * GP + tg * 8 + cp * 4];
                #pragma unroll
                for (int nt = 0; nt < 4; nt++) {
                    mma_tf32(c[mt][nt], aL.x, aH.x, aL.y, aH.y, bF[nt].x, bF[nt].y);
                    mma_tf32(c[mt][nt], aL.z, aH.z, aL.w, aH.w, bF[nt].z, bF[nt].w);
                }
            }
        }
        st ^= 1;
    }

    #pragma unroll
    for (int mt = 0; mt < 4; mt++) {
        int r0 = m0 + warp_m * 64 + mt * 16 + gid;
        #pragma unroll
        for (int nt = 0; nt < 4; nt++) {
            int col = n0 + warp_n * 32 + nt * 8 + tg * 2;
            float2 bb = *(const float2*)&bias[col];
            float v00 = alpha * (c[mt][nt][0] + bb.x);
            float v01 = alpha * (c[mt][nt][1] + bb.y);
            float v10 = alpha * (c[mt][nt][2] + bb.x);
            float v11 = alpha * (c[mt][nt][3] + bb.y);
            if (OUT == 0) {
                float* C = (float*)Cout;
                *(float2*)&C[(size_t)r0 * 1024 + col] = make_float2(v00, v01);
                *(float2*)&C[(size_t)(r0 + 8) * 1024 + col] = make_float2(v10, v11);
            } else {
                uint32_t* C = (uint32_t*)Cout;
                uint2 u0 = { f2tf32(v00), f2tf32(v01) };
                *(uint2*)&C[(size_t)r0 * 1024 + col] = u0;
                uint2 u1 = { f2tf32(v10), f2tf32(v11) };
                *(uint2*)&C[(size_t)(r0 + 8) * 1024 + col] = u1;
            }
        }
    }
}

// ---------------------------------------------------------------------------
// TF32 flash attention (round-6 passing core). Epilogue writes packed-32 O
// directly — WITH the batch offset (the round-5/7 bug was omitting b*SEQ).
// smem = 106496 B.
// ---------------------------------------------------------------------------
#define KS_P 68
#define VS_P 72
#define PS_P 68
#define K_STAGE (64 * KS_P)
#define V_STAGE (64 * VS_P)
#define ATTN_SMEM ((2 * K_STAGE + 2 * V_STAGE + 128 * PS_P) * 4)

__global__ __launch_bounds__(256)
void attn_tf32(const uint32_t* __restrict__ Q,
               const uint32_t* __restrict__ K,
               const uint32_t* __restrict__ V,
               uint32_t* __restrict__ O)
{
    extern __shared__ uint32_t sa[];
    uint32_t* Kbuf = sa;                         // [2][64][KS_P] tf32
    uint32_t* Vbuf = sa + 2 * K_STAGE;           // [2][64][VS_P] tf32
    uint32_t* Ps   = sa + 2 * K_STAGE + 2 * V_STAGE;  // [128][PS_P] tf32

    const int tid  = threadIdx.x;
    const int lane = tid & 31;
    const int wid  = tid >> 5;
    const int gid  = lane >> 2;
    const int tg   = lane & 3;
    const int row_base = wid * 16;

    const int q0 = blockIdx.x * 128;
    const int h  = blockIdx.y;
    const int b  = blockIdx.z;

    const uint32_t* Qb = Q + (size_t)b * SEQ * D_MODEL + h * D_K;
    const uint32_t* Kb = K + (size_t)b * SEQ * D_MODEL + h * D_K;
    const uint32_t* Vb = V + (size_t)b * SEQ * D_MODEL + h * D_K;

    uint32_t qf[8][4];
    {
        const uint32_t* qr0 = Qb + (size_t)(q0 + row_base + gid) * D_MODEL;
        const uint32_t* qr1 = qr0 + (size_t)8 * D_MODEL;
        #pragma unroll
        for (int c8 = 0; c8 < 8; c8++) {
            qf[c8][0] = qr0[c8 * 8 + tg    ];
            qf[c8][1] = qr1[c8 * 8 + tg    ];
            qf[c8][2] = qr0[c8 * 8 + tg + 4];
            qf[c8][3] = qr1[c8 * 8 + tg + 4];
        }
    }

    #pragma unroll
    for (int i = 0; i < 4; i++) {
        int idx = tid + i * 256;
        int r = idx >> 4, c4 = (idx & 15) * 4;
        cpasync16(smem_u32(&Kbuf[r * KS_P + c4]), &Kb[(size_t)r * D_MODEL + c4]);
        cpasync16(smem_u32(&Vbuf[r * VS_P + c4]), &Vb[(size_t)r * D_MODEL + c4]);
    }
    cpasync_commit();

    float o[8][4];
    #pragma unroll
    for (int nt = 0; nt < 8; nt++)
        #pragma unroll
        for (int i = 0; i < 4; i++) o[nt][i] = 0.f;
    float m_i[2] = { -1e30f, -1e30f };
    float l_i[2] = { 0.f, 0.f };

    int st = 0;
    for (int kt = 0; kt < SEQ; kt += 64) {
        cpasync_wait<0>();
        __syncthreads();

        if (kt + 64 < SEQ) {
            uint32_t* Kd = Kbuf + (st ^ 1) * K_STAGE;
            uint32_t* Vd = Vbuf + (st ^ 1) * V_STAGE;
            #pragma unroll
            for (int i = 0; i < 4; i++) {
                int idx = tid + i * 256;
                int r = idx >> 4, c4 = (idx & 15) * 4;
                cpasync16(smem_u32(&Kd[r * KS_P + c4]),
                          &Kb[(size_t)(kt + 64 + r) * D_MODEL + c4]);
                cpasync16(smem_u32(&Vd[r * VS_P + c4]),
                          &Vb[(size_t)(kt + 64 + r) * D_MODEL + c4]);
            }
            cpasync_commit();
        }

        const uint32_t* Ks = Kbuf + st * K_STAGE;
        const uint32_t* Vs = Vbuf + st * V_STAGE;

        float s[8][4];
        #pragma unroll
        for (int nt = 0; nt < 8; nt++)
            #pragma unroll
            for (int i = 0; i < 4; i++) s[nt][i] = 0.f;

        #pragma unroll
        for (int c8 = 0; c8 < 8; c8++) {
            int ks = c8 * 8;
            #pragma unroll
            for (int nt = 0; nt < 8; nt++) {
                uint32_t b0 = Ks[(nt * 8 + gid) * KS_P + ks + tg];
                uint32_t b1 = Ks[(nt * 8 + gid) * KS_P + ks + tg + 4];
                mma_tf32(s[nt], qf[c8][0], qf[c8][1], qf[c8][2], qf[c8][3], b0, b1);
            }
        }

        #pragma unroll
        for (int half = 0; half < 2; half++) {
            float mx = -1e30f;
            #pragma unroll
            for (int nt = 0; nt < 8; nt++)
                mx = fmaxf(mx, fmaxf(s[nt][half * 2], s[nt][half * 2 + 1]));
            mx = fmaxf(mx, __shfl_xor_sync(0xffffffffu, mx, 1));
            mx = fmaxf(mx, __shfl_xor_sync(0xffffffffu, mx, 2));

            float mnew = fmaxf(m_i[half], mx);
            float corr = __expf(m_i[half] - mnew);
            float rs = 0.f;
            #pragma unroll
            for (int nt = 0; nt < 8; nt++) {
                s[nt][half * 2]     = __expf(s[nt][half * 2]     - mnew);
                s[nt][half * 2 + 1] = __expf(s[nt][half * 2 + 1] - mnew);
                rs += s[nt][half * 2] + s[nt][half * 2 + 1];
            }
            rs += __shfl_xor_sync(0xffffffffu, rs, 1);
            rs += __shfl_xor_sync(0xffffffffu, rs, 2);

            l_i[half] = l_i[half] * corr + rs;
            m_i[half] = mnew;
            #pragma unroll
            for (int nt = 0; nt < 8; nt++) {
                o[nt][half * 2]     *= corr;
                o[nt][half * 2 + 1] *= corr;
            }
        }

        __syncwarp();
        #pragma unroll
        for (int nt = 0; nt < 8; nt++) {
            int cc = nt * 8 + tg * 2;
            Ps[(row_base + gid    ) * PS_P + cc    ] = f2tf32(s[nt][0]);
            Ps[(row_base + gid    ) * PS_P + cc + 1] = f2tf32(s[nt][1]);
            Ps[(row_base + gid + 8) * PS_P + cc    ] = f2tf32(s[nt][2]);
            Ps[(row_base + gid + 8) * PS_P + cc + 1] = f2tf32(s[nt][3]);
        }
        __syncwarp();

        #pragma unroll
        for (int c8 = 0; c8 < 8; c8++) {
            int ks = c8 * 8;
            uint32_t a0 = Ps[(row_base + gid    ) * PS_P + ks + tg];
            uint32_t a1 = Ps[(row_base + gid + 8) * PS_P + ks + tg];
            uint32_t a2 = Ps[(row_base + gid    ) * PS_P + ks + tg + 4];
            uint32_t a3 = Ps[(row_base + gid + 8) * PS_P + ks + tg + 4];
            #pragma unroll
            for (int nt = 0; nt < 8; nt++) {
                uint32_t b0 = Vs[(ks + tg    ) * VS_P + nt * 8 + gid];
                uint32_t b1 = Vs[(ks + tg + 4) * VS_P + nt * 8 + gid];
                mma_tf32(o[nt], a0, a1, a2, a3, b0, b1);
            }
        }
        st ^= 1;
    }

    // Epilogue: normalize, write packed-32 O. r0 is the GLOBAL token row —
    // b*SEQ included (this was the round-5/7 bug).
    float inv0 = 1.0f / l_i[0];
    float inv1 = 1.0f / l_i[1];
    int r0 = b * SEQ + q0 + row_base + gid;
    #pragma unroll
    for (int nt = 0; nt < 8; nt++) {
        int c0 = h * D_K + nt * 8 + tg * 2;
        int c1 = c0 + 1;
        size_t a0 = (size_t)r0 * D_MODEL + (c0 & ~31) + phys32(c0 & 31);
        size_t a1 = (size_t)r0 * D_MODEL + (c1 & ~31) + phys32(c1 & 31);
        O[a0] = f2tf32(o[nt][0] * inv0);
        O[a1] = f2tf32(o[nt][1] * inv0);
        O[a0 + 8 * D_MODEL] = f2tf32(o[nt][2] * inv1);
        O[a1 + 8 * D_MODEL] = f2tf32(o[nt][3] * inv1);
    }
}

// ---------------------------------------------------------------------------
// kernel_launch — inputs: q, k, v, w_q, b_q, w_k, b_k, w_v, b_v, w_o, b_o
// ---------------------------------------------------------------------------
extern "C" void kernel_launch(void* const* d_in, const int* in_sizes, int n_in,
                              void* d_out, int out_size)
{
    const float* q   = (const float*)d_in[0];
    const float* k   = (const float*)d_in[1];
    const float* v   = (const float*)d_in[2];
    const float* w_q = (const float*)d_in[3];
    const float* b_q = (const float*)d_in[4];
    const float* w_k = (const float*)d_in[5];
    const float* b_k = (const float*)d_in[6];
    const float* w_v = (const float*)d_in[7];
    const float* b_v = (const float*)d_in[8];
    const float* w_o = (const float*)d_in[9];
    const float* b_o = (const float*)d_in[10];
    float* out = (float*)d_out;

    uint32_t *tq, *tk, *tv, *twq, *twk, *twv, *two, *gq, *gk, *gv, *go;
    cudaGetSymbolAddress((void**)&tq,  t_q);
    cudaGetSymbolAddress((void**)&tk,  t_k);
    cudaGetSymbolAddress((void**)&tv,  t_v);
    cudaGetSymbolAddress((void**)&twq, t_wq);
    cudaGetSymbolAddress((void**)&twk, t_wk);
    cudaGetSymbolAddress((void**)&twv, t_wv);
    cudaGetSymbolAddress((void**)&two, t_wo);
    cudaGetSymbolAddress((void**)&gq,  g_Q);
    cudaGetSymbolAddress((void**)&gk,  g_K);
    cudaGetSymbolAddress((void**)&gv,  g_V);
    cudaGetSymbolAddress((void**)&go,  g_O);

    cudaFuncSetAttribute(gemm_tf32<0>, cudaFuncAttributeMaxDynamicSharedMemorySize, GEMM_SMEM);
    cudaFuncSetAttribute(gemm_tf32<1>, cudaFuncAttributeMaxDynamicSharedMemorySize, GEMM_SMEM);
    cudaFuncSetAttribute(attn_tf32,    cudaFuncAttributeMaxDynamicSharedMemorySize, ATTN_SMEM);

    // Pre-pass: 2 launches total
    const int n_act = M_ROWS * D_MODEL;
    dim3 act_grid(n_act / 256, 3);
    pack_act3_kernel<<<act_grid, 256>>>(q, k, v, tq, tk, tv, n_act);
    dim3 wt_grid(32, 32, 4), wt_block(32, 8);
    pack_wT4_kernel<<<wt_grid, wt_block>>>(w_q, w_k, w_v, w_o, twq, twk, twv, two);

    dim3 gemm_grid(D_MODEL / 128, M_ROWS / 128);  // (8, 32)
    gemm_tf32<1><<<gemm_grid, 256, GEMM_SMEM>>>(tq, twq, b_q, gq, 0.125f);
    gemm_tf32<1><<<gemm_grid, 256, GEMM_SMEM>>>(tk, twk, b_k, gk, 1.0f);
    gemm_tf32<1><<<gemm_grid, 256, GEMM_SMEM>>>(tv, twv, b_v, gv, 1.0f);

    dim3 attn_grid(SEQ / 128, N_HEADS, BATCH);    // (16, 16, 2)
    attn_tf32<<<attn_grid, 256, ATTN_SMEM>>>(gq, gk, gv, go);

    gemm_tf32<0><<<gemm_grid, 256, GEMM_SMEM>>>(go, two, b_o, out, 1.0f);
}

// round 9
// speedup vs baseline: 1.1502x; 1.0158x over previous
#include <cuda_runtime.h>
#include <cstdint>

#define D_MODEL 1024
#define N_HEADS 16
#define D_K     64
#define BATCH   2
#define SEQ     2048
#define M_ROWS  (BATCH * SEQ)   // 4096

// Scratch (allocation-free rule: __device__ globals). tf32 payloads as u32 bits.
__device__ uint32_t t_q [M_ROWS * D_MODEL];   // natural tf32 acts
__device__ uint32_t t_k [M_ROWS * D_MODEL];
__device__ uint32_t t_v [M_ROWS * D_MODEL];
__device__ uint32_t t_wq[D_MODEL * D_MODEL];  // natural tf32 weights [k][n]
__device__ uint32_t t_wk[D_MODEL * D_MODEL];
__device__ uint32_t t_wv[D_MODEL * D_MODEL];
__device__ uint32_t t_wo[D_MODEL * D_MODEL];
__device__ uint32_t g_Q [M_ROWS * D_MODEL];   // natural [token][1024], pre-scaled tf32
__device__ uint32_t g_K [M_ROWS * D_MODEL];   // [token][head*64 + pack16] tf32
__device__ uint32_t g_V [M_ROWS * D_MODEL];   // [(b*16+h)*64+d][token pack16/64] tf32
__device__ uint32_t g_O [M_ROWS * D_MODEL];   // natural tf32 (attn out)

__device__ __forceinline__ uint32_t f2tf32(float x) {
    uint32_t r;
    asm("cvt.rna.tf32.f32 %0, %1;" : "=r"(r) : "f"(x));
    return r;
}

__device__ __forceinline__ void mma_tf32(float c[4],
                                         uint32_t a0, uint32_t a1, uint32_t a2, uint32_t a3,
                                         uint32_t b0, uint32_t b1) {
    asm volatile(
        "mma.sync.aligned.m16n8k8.row.col.f32.tf32.tf32.f32 "
        "{%0,%1,%2,%3}, {%4,%5,%6,%7}, {%8,%9}, {%0,%1,%2,%3};"
        : "+f"(c[0]), "+f"(c[1]), "+f"(c[2]), "+f"(c[3])
        : "r"(a0), "r"(a1), "r"(a2), "r"(a3), "r"(b0), "r"(b1));
}

__device__ __forceinline__ uint32_t smem_u32(const void* p) {
    return (uint32_t)__cvta_generic_to_shared(p);
}
__device__ __forceinline__ void cpasync16(uint32_t dst, const void* src) {
    asm volatile("cp.async.cg.shared.global [%0], [%1], 16;" :: "r"(dst), "l"(src));
}
__device__ __forceinline__ void cpasync_commit() {
    asm volatile("cp.async.commit_group;");
}
template<int N> __device__ __forceinline__ void cpasync_wait() {
    asm volatile("cp.async.wait_group %0;" :: "n"(N));
}

// pack within a 64-element vector (attn frag order):
// c = c8*8 + tg + sel*4 -> chunk = (c8>>1)*4 + tg, pos = (c8&1)*2 + sel
__device__ __forceinline__ int phys16(int c) {
    return (((c >> 4) & 3) * 4 + (c & 3)) * 4 + ((c >> 3) & 1) * 2 + ((c >> 2) & 1);
}

// ---------------------------------------------------------------------------
// Pre-pass: pure fp32 -> tf32 conversion, natural layout. Fused launches.
// ---------------------------------------------------------------------------
__global__ __launch_bounds__(256)
void cvt3_kernel(const float4* __restrict__ q, const float4* __restrict__ k,
                 const float4* __restrict__ v,
                 uint4* __restrict__ tq, uint4* __restrict__ tk,
                 uint4* __restrict__ tv, int n4)
{
    int i = blockIdx.x * 256 + threadIdx.x;
    if (i >= n4) return;
    const float4* in = (blockIdx.y == 0) ? q : (blockIdx.y == 1) ? k : v;
    uint4*       out = (blockIdx.y == 0) ? tq : (blockIdx.y == 1) ? tk : tv;
    float4 a = in[i];
    uint4 u = { f2tf32(a.x), f2tf32(a.y), f2tf32(a.z), f2tf32(a.w) };
    out[i] = u;
}

__global__ __launch_bounds__(256)
void cvt4_kernel(const float4* __restrict__ wq, const float4* __restrict__ wk,
                 const float4* __restrict__ wv, const float4* __restrict__ wo,
                 uint4* __restrict__ twq, uint4* __restrict__ twk,
                 uint4* __restrict__ twv, uint4* __restrict__ two, int n4)
{
    int i = blockIdx.x * 256 + threadIdx.x;
    if (i >= n4) return;
    const float4* in = (blockIdx.y == 0) ? wq : (blockIdx.y == 1) ? wk :
                       (blockIdx.y == 2) ? wv : wo;
    uint4*       out = (blockIdx.y == 0) ? twq : (blockIdx.y == 1) ? twk :
                       (blockIdx.y == 2) ? twv : two;
    float4 a = in[i];
    uint4 u = { f2tf32(a.x), f2tf32(a.y), f2tf32(a.z), f2tf32(a.w) };
    out[i] = u;
}

// ---------------------------------------------------------------------------
// TF32 GEMM — round-4 core (natural layouts, scalar frag LDS, BK=32,
// 2-stage cp.async, 256 thr, warp tile 64x32, pitches 36/136).
// C = alpha*(A@W + bias).
// OUT: 0=fp32 natural, 1=tf32 natural, 2=attn-K pack16, 3=V^T pack16.
// ---------------------------------------------------------------------------
#define GA_P 36
#define GB_P 136
#define GEMM_STAGE_A (128 * GA_P)
#define GEMM_STAGE_B (32 * GB_P)
#define GEMM_SMEM ((2 * (GEMM_STAGE_A + GEMM_STAGE_B)) * 4)

template<int OUT>
__global__ __launch_bounds__(256)
void gemm_tf32(const uint32_t* __restrict__ A,
               const uint32_t* __restrict__ W,
               const float* __restrict__ bias,
               void* __restrict__ Cout,
               float alpha)
{
    extern __shared__ uint32_t sg[];
    uint32_t* Asm = sg;                        // [2][128][GA_P]
    uint32_t* Bsm = sg + 2 * GEMM_STAGE_A;     // [2][32][GB_P]

    const int tid  = threadIdx.x;
    const int lane = tid & 31;
    const int gid  = lane >> 2;
    const int tg   = lane & 3;
    const int wid  = tid >> 5;
    const int warp_m = wid & 1;
    const int warp_n = wid >> 1;
    const int m0 = blockIdx.y * 128;
    const int n0 = blockIdx.x * 128;

    float c[4][4][4];
    #pragma unroll
    for (int mt = 0; mt < 4; mt++)
        #pragma unroll
        for (int nt = 0; nt < 4; nt++)
            #pragma unroll
            for (int i = 0; i < 4; i++) c[mt][nt][i] = 0.f;

    // Prologue stage 0
    #pragma unroll
    for (int i = 0; i < 4; i++) {
        int idx = tid + i * 256;
        int row = idx >> 3, kk = (idx & 7) * 4;
        cpasync16(smem_u32(&Asm[row * GA_P + kk]),
                  &A[(size_t)(m0 + row) * D_MODEL + kk]);
    }
    #pragma unroll
    for (int i = 0; i < 4; i++) {
        int idx = tid + i * 256;
        int kk = idx >> 5, col = (idx & 31) * 4;
        cpasync16(smem_u32(&Bsm[kk * GB_P + col]),
                  &W[(size_t)kk * D_MODEL + n0 + col]);
    }
    cpasync_commit();

    int st = 0;
    for (int k0 = 0; k0 < D_MODEL; k0 += 32) {
        cpasync_wait<0>();
        __syncthreads();

        if (k0 + 32 < D_MODEL) {
            uint32_t* Ad = Asm + (st ^ 1) * GEMM_STAGE_A;
            uint32_t* Bd = Bsm + (st ^ 1) * GEMM_STAGE_B;
            #pragma unroll
            for (int i = 0; i < 4; i++) {
                int idx = tid + i * 256;
                int row = idx >> 3, kk = (idx & 7) * 4;
                cpasync16(smem_u32(&Ad[row * GA_P + kk]),
                          &A[(size_t)(m0 + row) * D_MODEL + k0 + 32 + kk]);
            }
            #pragma unroll
            for (int i = 0; i < 4; i++) {
                int idx = tid + i * 256;
                int kk = idx >> 5, col = (idx & 31) * 4;
                cpasync16(smem_u32(&Bd[kk * GB_P + col]),
                          &W[(size_t)(k0 + 32 + kk) * D_MODEL + n0 + col]);
            }
            cpasync_commit();
        }

        const uint32_t* As = Asm + st * GEMM_STAGE_A;
        const uint32_t* Bq = Bsm + st * GEMM_STAGE_B;

        #pragma unroll
        for (int ks = 0; ks < 32; ks += 8) {
            uint32_t af[4][4], bf[4][2];
            #pragma unroll
            for (int mt = 0; mt < 4; mt++) {
                int r = warp_m * 64 + mt * 16;
                af[mt][0] = As[(r + gid    ) * GA_P + ks + tg];
                af[mt][1] = As[(r + gid + 8) * GA_P + ks + tg];
                af[mt][2] = As[(r + gid    ) * GA_P + ks + tg + 4];
                af[mt][3] = As[(r + gid + 8) * GA_P + ks + tg + 4];
            }
            #pragma unroll
            for (int nt = 0; nt < 4; nt++) {
                int cb = warp_n * 32 + nt * 8;
                bf[nt][0] = Bq[(ks + tg    ) * GB_P + cb + gid];
                bf[nt][1] = Bq[(ks + tg + 4) * GB_P + cb + gid];
            }
            #pragma unroll
            for (int mt = 0; mt < 4; mt++)
                #pragma unroll
                for (int nt = 0; nt < 4; nt++)
                    mma_tf32(c[mt][nt], af[mt][0], af[mt][1], af[mt][2], af[mt][3],
                             bf[nt][0], bf[nt][1]);
        }
        st ^= 1;
    }

    #pragma unroll
    for (int mt = 0; mt < 4; mt++) {
        int r0 = m0 + warp_m * 64 + mt * 16 + gid;
        #pragma unroll
        for (int nt = 0; nt < 4; nt++) {
            int col = n0 + warp_n * 32 + nt * 8 + tg * 2;
            float2 bb = *(const float2*)&bias[col];
            float v00 = alpha * (c[mt][nt][0] + bb.x);
            float v01 = alpha * (c[mt][nt][1] + bb.y);
            float v10 = alpha * (c[mt][nt][2] + bb.x);
            float v11 = alpha * (c[mt][nt][3] + bb.y);
            if (OUT == 0) {
                float* C = (float*)Cout;
                *(float2*)&C[(size_t)r0 * D_MODEL + col] = make_float2(v00, v01);
                *(float2*)&C[(size_t)(r0 + 8) * D_MODEL + col] = make_float2(v10, v11);
            } else if (OUT == 1) {
                uint32_t* C = (uint32_t*)Cout;
                uint2 u0 = { f2tf32(v00), f2tf32(v01) };
                *(uint2*)&C[(size_t)r0 * D_MODEL + col] = u0;
                uint2 u1 = { f2tf32(v10), f2tf32(v11) };
                *(uint2*)&C[(size_t)(r0 + 8) * D_MODEL + col] = u1;
            } else if (OUT == 2) {
                // attn-K pack16 within each head's 64 cols
                uint32_t* C = (uint32_t*)Cout;
                int h = col >> 6, cc = col & 63;
                int p0 = phys16(cc), p1 = phys16(cc + 1);
                size_t base0 = (size_t)r0 * D_MODEL + h * 64;
                size_t base1 = (size_t)(r0 + 8) * D_MODEL + h * 64;
                C[base0 + p0] = f2tf32(v00);
                C[base0 + p1] = f2tf32(v01);
                C[base1 + p0] = f2tf32(v10);
                C[base1 + p1] = f2tf32(v11);
            } else {
                // V^T pack16: [(b*16+h)*64+d][tok_tile + phys16(tok&63)]
                uint32_t* C = (uint32_t*)Cout;
                int bi = r0 >> 11, tok = r0 & 2047;
                int h = col >> 6, d = col & 63;
                int w0 = phys16(tok & 63), w1 = phys16((tok + 8) & 63);
                size_t rowA = ((size_t)(bi * 16 + h) * 64 + d) * 2048 + (tok & ~63);
                C[rowA + w0] = f2tf32(v00);
                C[rowA + 2048 + w0] = f2tf32(v01);
                C[rowA + w1] = f2tf32(v10);
                C[rowA + 2048 + w1] = f2tf32(v11);
            }
        }
    }
}

// ---------------------------------------------------------------------------
// TF32 flash attention — round-5 packed-fragment mainloop (values verified
// bit-identical to the natural path via the round-5/7 rel_err identity).
// CTA = 128 q rows x (b,h). 8 warps x 16 rows. K: 2-stage cp.async;
// V: single buffer, split commit groups. Pitch 80 (conflict-free LDS.128).
// Epilogue: NATURAL tf32 write with the b*SEQ offset (known-good form).
// smem = 102400 B.
// ---------------------------------------------------------------------------
#define AK_P 80
#define AK_STAGE (64 * AK_P)
#define AV_STAGE (64 * AK_P)
#define AP_SIZE  (128 * AK_P)
#define ATTN_SMEM ((2 * AK_STAGE + AV_STAGE + AP_SIZE) * 4)

__global__ __launch_bounds__(256, 2)
void attn_tf32(const uint32_t* __restrict__ Q,
               const uint32_t* __restrict__ K,
               const uint32_t* __restrict__ V,
               uint32_t* __restrict__ O)
{
    extern __shared__ uint32_t sa[];
    uint32_t* Kbuf = sa;                               // [2][64][80]
    uint32_t* Vbuf = sa + 2 * AK_STAGE;                // [64][80]
    uint32_t* Ps   = sa + 2 * AK_STAGE + AV_STAGE;     // [128][80]

    const int tid  = threadIdx.x;
    const int lane = tid & 31;
    const int wid  = tid >> 5;
    const int gid  = lane >> 2;
    const int tg   = lane & 3;
    const int rb   = wid * 16;

    const int q0 = blockIdx.x * 128;
    const int h  = blockIdx.y;
    const int b  = blockIdx.z;

    const uint32_t* Qb  = Q + (size_t)b * SEQ * D_MODEL + h * D_K;
    const uint32_t* Kb  = K + (size_t)b * SEQ * D_MODEL + h * D_K;
    const uint32_t* Vtb = V + ((size_t)(b * 16 + h) * 64) * 2048;

    // Q fragments (pre-scaled tf32, natural layout)
    uint32_t qf[8][4];
    {
        const uint32_t* qr0 = Qb + (size_t)(q0 + rb + gid) * D_MODEL;
        const uint32_t* qr1 = qr0 + (size_t)8 * D_MODEL;
        #pragma unroll
        for (int c8 = 0; c8 < 8; c8++) {
            qf[c8][0] = qr0[c8 * 8 + tg    ];
            qf[c8][1] = qr1[c8 * 8 + tg    ];
            qf[c8][2] = qr0[c8 * 8 + tg + 4];
            qf[c8][3] = qr1[c8 * 8 + tg + 4];
        }
    }

    // Prologue: K0 (group), V0 (group)
    #pragma unroll
    for (int i = 0; i < 4; i++) {
        int idx = tid + i * 256;
        int r = idx >> 4, ch = idx & 15;
        cpasync16(smem_u32(&Kbuf[r * AK_P + ch * 4]), &Kb[(size_t)r * D_MODEL + ch * 4]);
    }
    cpasync_commit();
    #pragma unroll
    for (int i = 0; i < 4; i++) {
        int idx = tid + i * 256;
        int r = idx >> 4, ch = idx & 15;
        cpasync16(smem_u32(&Vbuf[r * AK_P + ch * 4]), &Vtb[(size_t)r * 2048 + ch * 4]);
    }
    cpasync_commit();

    float o[8][4];
    #pragma unroll
    for (int nt = 0; nt < 8; nt++)
        #pragma unroll
        for (int i = 0; i < 4; i++) o[nt][i] = 0.f;
    float m_i[2] = { -1e30f, -1e30f };
    float l_i[2] = { 0.f, 0.f };

    const int tgl0 = (tg * 2) & 3;
    const int tgl1 = (tg * 2 + 1) & 3;
    const int selp = tg >> 1;

    int st = 0;
    for (int kt = 0; kt < SEQ; kt += 64) {
        cpasync_wait<1>();           // K_cur done (V_cur may be pending)
        __syncthreads();

        if (kt + 64 < SEQ) {         // issue K_next
            uint32_t* Kd = Kbuf + (st ^ 1) * AK_STAGE;
            #pragma unroll
            for (int i = 0; i < 4; i++) {
                int idx = tid + i * 256;
                int r = idx >> 4, ch = idx & 15;
                cpasync16(smem_u32(&Kd[r * AK_P + ch * 4]),
                          &Kb[(size_t)(kt + 64 + r) * D_MODEL + ch * 4]);
            }
            cpasync_commit();
        }

        const uint32_t* Ks = Kbuf + st * AK_STAGE;

        // S = Q @ K^T
        float s[8][4];
        #pragma unroll
        for (int nt = 0; nt < 8; nt++)
            #pragma unroll
            for (int i = 0; i < 4; i++) s[nt][i] = 0.f;

        #pragma unroll
        for (int jj = 0; jj < 4; jj++) {
            #pragma unroll
            for (int nt = 0; nt < 8; nt++) {
                uint4 kf = *(const uint4*)&Ks[(nt * 8 + gid) * AK_P + (jj * 4 + tg) * 4];
                mma_tf32(s[nt], qf[2*jj][0], qf[2*jj][1], qf[2*jj][2], qf[2*jj][3],
                         kf.x, kf.y);
                mma_tf32(s[nt], qf[2*jj+1][0], qf[2*jj+1][1], qf[2*jj+1][2], qf[2*jj+1][3],
                         kf.z, kf.w);
            }
        }

        // Online softmax (rows rb+gid, rb+gid+8; quad reduce)
        #pragma unroll
        for (int half = 0; half < 2; half++) {
            float mx = -1e30f;
            #pragma unroll
            for (int nt = 0; nt < 8; nt++)
                mx = fmaxf(mx, fmaxf(s[nt][half * 2], s[nt][half * 2 + 1]));
            mx = fmaxf(mx, __shfl_xor_sync(0xffffffffu, mx, 1));
            mx = fmaxf(mx, __shfl_xor_sync(0xffffffffu, mx, 2));

            float mnew = fmaxf(m_i[half], mx);
            float corr = __expf(m_i[half] - mnew);
            float rs = 0.f;
            #pragma unroll
            for (int nt = 0; nt < 8; nt++) {
                s[nt][half * 2]     = __expf(s[nt][half * 2]     - mnew);
                s[nt][half * 2 + 1] = __expf(s[nt][half * 2 + 1] - mnew);
                rs += s[nt][half * 2] + s[nt][half * 2 + 1];
            }
            rs += __shfl_xor_sync(0xffffffffu, rs, 1);
            rs += __shfl_xor_sync(0xffffffffu, rs, 2);

            l_i[half] = l_i[half] * corr + rs;
            m_i[half] = mnew;
            #pragma unroll
            for (int nt = 0; nt < 8; nt++) {
                o[nt][half * 2]     *= corr;
                o[nt][half * 2 + 1] *= corr;
            }
        }

        // P -> smem, pack16 (warp-private rows)
        __syncwarp();
        #pragma unroll
        for (int nt = 0; nt < 8; nt++) {
            int ch0 = (nt >> 1) * 4 + tgl0;
            int ch1 = (nt >> 1) * 4 + tgl1;
            int pos = (nt & 1) * 2 + selp;
            Ps[(rb + gid    ) * AK_P + ch0 * 4 + pos] = f2tf32(s[nt][0]);
            Ps[(rb + gid    ) * AK_P + ch1 * 4 + pos] = f2tf32(s[nt][1]);
            Ps[(rb + gid + 8) * AK_P + ch0 * 4 + pos] = f2tf32(s[nt][2]);
            Ps[(rb + gid + 8) * AK_P + ch1 * 4 + pos] = f2tf32(s[nt][3]);
        }
        __syncwarp();

        // V_cur must be complete (and visible to all)
        if (kt + 64 < SEQ) cpasync_wait<1>(); else cpasync_wait<0>();
        __syncthreads();

        // O += P @ V
        #pragma unroll
        for (int jj = 0; jj < 4; jj++) {
            uint4 p0 = *(const uint4*)&Ps[(rb + gid    ) * AK_P + (jj * 4 + tg) * 4];
            uint4 p1 = *(const uint4*)&Ps[(rb + gid + 8) * AK_P + (jj * 4 + tg) * 4];
            #pragma unroll
            for (int nt = 0; nt < 8; nt++) {
                uint4 vf = *(const uint4*)&Vbuf[(nt * 8 + gid) * AK_P + (jj * 4 + tg) * 4];
                mma_tf32(o[nt], p0.x, p1.x, p0.y, p1.y, vf.x, vf.y);
                mma_tf32(o[nt], p0.z, p1.z, p0.w, p1.w, vf.z, vf.w);
            }
        }

        __syncthreads();   // all warps done reading V_cur (and K_cur)

        if (kt + 64 < SEQ) {   // issue V_next into the single V buffer
            #pragma unroll
            for (int i = 0; i < 4; i++) {
                int idx = tid + i * 256;
                int r = idx >> 4, ch = idx & 15;
                cpasync16(smem_u32(&Vbuf[r * AK_P + ch * 4]),
                          &Vtb[(size_t)r * 2048 + kt + 64 + ch * 4]);
            }
            cpasync_commit();
        }
        st ^= 1;
    }

    // Epilogue: normalize, NATURAL tf32 write (round-4/6 known-good form).
    float inv0 = 1.0f / l_i[0];
    float inv1 = 1.0f / l_i[1];
    uint32_t* Ob = O + (size_t)b * SEQ * D_MODEL + h * D_K;
    int r0 = q0 + rb + gid;
    #pragma unroll
    for (int nt = 0; nt < 8; nt++) {
        int col = nt * 8 + tg * 2;
        uint2 t0 = { f2tf32(o[nt][0] * inv0), f2tf32(o[nt][1] * inv0) };
        *(uint2*)&Ob[(size_t)r0 * D_MODEL + col] = t0;
        uint2 t1 = { f2tf32(o[nt][2] * inv1), f2tf32(o[nt][3] * inv1) };
        *(uint2*)&Ob[(size_t)(r0 + 8) * D_MODEL + col] = t1;
    }
}

// ---------------------------------------------------------------------------
// kernel_launch — inputs: q, k, v, w_q, b_q, w_k, b_k, w_v, b_v, w_o, b_o
// ---------------------------------------------------------------------------
extern "C" void kernel_launch(void* const* d_in, const int* in_sizes, int n_in,
                              void* d_out, int out_size)
{
    const float* q   = (const float*)d_in[0];
    const float* k   = (const float*)d_in[1];
    const float* v   = (const float*)d_in[2];
    const float* w_q = (const float*)d_in[3];
    const float* b_q = (const float*)d_in[4];
    const float* w_k = (const float*)d_in[5];
    const float* b_k = (const float*)d_in[6];
    const float* w_v = (const float*)d_in[7];
    const float* b_v = (const float*)d_in[8];
    const float* w_o = (const float*)d_in[9];
    const float* b_o = (const float*)d_in[10];
    float* out = (float*)d_out;

    uint32_t *tq, *tk, *tv, *twq, *twk, *twv, *two, *gq, *gk, *gv, *go;
    cudaGetSymbolAddress((void**)&tq,  t_q);
    cudaGetSymbolAddress((void**)&tk,  t_k);
    cudaGetSymbolAddress((void**)&tv,  t_v);
    cudaGetSymbolAddress((void**)&twq, t_wq);
    cudaGetSymbolAddress((void**)&twk, t_wk);
    cudaGetSymbolAddress((void**)&twv, t_wv);
    cudaGetSymbolAddress((void**)&two, t_wo);
    cudaGetSymbolAddress((void**)&gq,  g_Q);
    cudaGetSymbolAddress((void**)&gk,  g_K);
    cudaGetSymbolAddress((void**)&gv,  g_V);
    cudaGetSymbolAddress((void**)&go,  g_O);

    cudaFuncSetAttribute(gemm_tf32<0>, cudaFuncAttributeMaxDynamicSharedMemorySize, GEMM_SMEM);
    cudaFuncSetAttribute(gemm_tf32<1>, cudaFuncAttributeMaxDynamicSharedMemorySize, GEMM_SMEM);
    cudaFuncSetAttribute(gemm_tf32<2>, cudaFuncAttributeMaxDynamicSharedMemorySize, GEMM_SMEM);
    cudaFuncSetAttribute(gemm_tf32<3>, cudaFuncAttributeMaxDynamicSharedMemorySize, GEMM_SMEM);
    cudaFuncSetAttribute(attn_tf32,    cudaFuncAttributeMaxDynamicSharedMemorySize, ATTN_SMEM);

    // Pre-pass: pure tf32 conversion (2 launches)
    const int n4_act = M_ROWS * D_MODEL / 4;      // 1048576
    const int n4_w   = D_MODEL * D_MODEL / 4;     // 262144
    dim3 act_grid(n4_act / 256, 3);
    cvt3_kernel<<<act_grid, 256>>>((const float4*)q, (const float4*)k, (const float4*)v,
                                   (uint4*)tq, (uint4*)tk, (uint4*)tv, n4_act);
    dim3 w_grid(n4_w / 256, 4);
    cvt4_kernel<<<w_grid, 256>>>((const float4*)w_q, (const float4*)w_k,
                                 (const float4*)w_v, (const float4*)w_o,
                                 (uint4*)twq, (uint4*)twk, (uint4*)twv, (uint4*)two, n4_w);

    dim3 gemm_grid(D_MODEL / 128, M_ROWS / 128);  // (8, 32)
    gemm_tf32<1><<<gemm_grid, 256, GEMM_SMEM>>>(tq, twq, b_q, gq, 0.125f);  // Q natural
    gemm_tf32<2><<<gemm_grid, 256, GEMM_SMEM>>>(tk, twk, b_k, gk, 1.0f);    // K pack16
    gemm_tf32<3><<<gemm_grid, 256, GEMM_SMEM>>>(tv, twv, b_v, gv, 1.0f);    // V^T pack16

    dim3 attn_grid(SEQ / 128, N_HEADS, BATCH);    // (16, 16, 2)
    attn_tf32<<<attn_grid, 256, ATTN_SMEM>>>(gq, gk, gv, go);

    gemm_tf32<0><<<gemm_grid, 256, GEMM_SMEM>>>(go, two, b_o, out, 1.0f);
}

// round 11
// speedup vs baseline: 1.5408x; 1.3395x over previous
#include <cuda_runtime.h>
#include <cuda_fp16.h>
#include <cstdint>

#define D_MODEL 1024
#define N_HEADS 16
#define D_K     64
#define BATCH   2
#define SEQ     2048
#define M_ROWS  (BATCH * SEQ)   // 4096

// Scratch (allocation-free rule: __device__ globals).
__device__ uint32_t t_q [M_ROWS * D_MODEL];   // natural tf32 acts
__device__ uint32_t t_k [M_ROWS * D_MODEL];
__device__ uint32_t t_v [M_ROWS * D_MODEL];
__device__ uint32_t t_wq[D_MODEL * D_MODEL];  // natural tf32 weights [k][n]
__device__ uint32_t t_wk[D_MODEL * D_MODEL];
__device__ uint32_t t_wv[D_MODEL * D_MODEL];
__device__ uint32_t t_wo[D_MODEL * D_MODEL];
__device__ uint32_t g_Q [M_ROWS * D_MODEL / 2];   // fp16 natural [token][1024h], pre-scaled
__device__ uint32_t g_K [M_ROWS * D_MODEL / 2];   // fp16 natural
__device__ uint32_t g_V [M_ROWS * D_MODEL / 2];   // fp16 V^T: [(b*16+h)*64+d][2048 halves]
__device__ uint32_t g_O [M_ROWS * D_MODEL];       // tf32 natural (attn out)

__device__ __forceinline__ uint32_t f2tf32(float x) {
    uint32_t r;
    asm("cvt.rna.tf32.f32 %0, %1;" : "=r"(r) : "f"(x));
    return r;
}
__device__ __forceinline__ uint32_t pack_h2(float lo, float hi) {
    __half2 h = __floats2half2_rn(lo, hi);   // .x = lo (low 16 bits)
    return *(uint32_t*)&h;
}

__device__ __forceinline__ void mma_tf32(float c[4],
                                         uint32_t a0, uint32_t a1, uint32_t a2, uint32_t a3,
                                         uint32_t b0, uint32_t b1) {
    asm volatile(
        "mma.sync.aligned.m16n8k8.row.col.f32.tf32.tf32.f32 "
        "{%0,%1,%2,%3}, {%4,%5,%6,%7}, {%8,%9}, {%0,%1,%2,%3};"
        : "+f"(c[0]), "+f"(c[1]), "+f"(c[2]), "+f"(c[3])
        : "r"(a0), "r"(a1), "r"(a2), "r"(a3), "r"(b0), "r"(b1));
}
__device__ __forceinline__ void mma_f16(float c[4],
                                        uint32_t a0, uint32_t a1, uint32_t a2, uint32_t a3,
                                        uint32_t b0, uint32_t b1) {
    asm volatile(
        "mma.sync.aligned.m16n8k16.row.col.f32.f16.f16.f32 "
        "{%0,%1,%2,%3}, {%4,%5,%6,%7}, {%8,%9}, {%0,%1,%2,%3};"
        : "+f"(c[0]), "+f"(c[1]), "+f"(c[2]), "+f"(c[3])
        : "r"(a0), "r"(a1), "r"(a2), "r"(a3), "r"(b0), "r"(b1));
}

__device__ __forceinline__ uint32_t smem_u32(const void* p) {
    return (uint32_t)__cvta_generic_to_shared(p);
}
__device__ __forceinline__ void cpasync16(uint32_t dst, const void* src) {
    asm volatile("cp.async.cg.shared.global [%0], [%1], 16;" :: "r"(dst), "l"(src));
}
__device__ __forceinline__ void cpasync_commit() {
    asm volatile("cp.async.commit_group;");
}
template<int N> __device__ __forceinline__ void cpasync_wait() {
    asm volatile("cp.async.wait_group %0;" :: "n"(N));
}

// ---------------------------------------------------------------------------
// Pre-pass: fp32 -> tf32, natural layouts (round-4 form, fused launches).
// ---------------------------------------------------------------------------
__global__ __launch_bounds__(256)
void cvt3_kernel(const float4* __restrict__ q, const float4* __restrict__ k,
                 const float4* __restrict__ v,
                 uint4* __restrict__ tq, uint4* __restrict__ tk,
                 uint4* __restrict__ tv, int n4)
{
    int i = blockIdx.x * 256 + threadIdx.x;
    if (i >= n4) return;
    const float4* in = (blockIdx.y == 0) ? q : (blockIdx.y == 1) ? k : v;
    uint4*       out = (blockIdx.y == 0) ? tq : (blockIdx.y == 1) ? tk : tv;
    float4 a = in[i];
    uint4 u = { f2tf32(a.x), f2tf32(a.y), f2tf32(a.z), f2tf32(a.w) };
    out[i] = u;
}

__global__ __launch_bounds__(256)
void cvt4_kernel(const float4* __restrict__ wq, const float4* __restrict__ wk,
                 const float4* __restrict__ wv, const float4* __restrict__ wo,
                 uint4* __restrict__ twq, uint4* __restrict__ twk,
                 uint4* __restrict__ twv, uint4* __restrict__ two, int n4)
{
    int i = blockIdx.x * 256 + threadIdx.x;
    if (i >= n4) return;
    const float4* in = (blockIdx.y == 0) ? wq : (blockIdx.y == 1) ? wk :
                       (blockIdx.y == 2) ? wv : wo;
    uint4*       out = (blockIdx.y == 0) ? twq : (blockIdx.y == 1) ? twk :
                       (blockIdx.y == 2) ? twv : two;
    float4 a = in[i];
    uint4 u = { f2tf32(a.x), f2tf32(a.y), f2tf32(a.z), f2tf32(a.w) };
    out[i] = u;
}

// ---------------------------------------------------------------------------
// TF32 GEMM — round-4 core verbatim (natural layouts, scalar frags, BK=32,
// 2-stage cp.async, 256 thr, warp tile 64x32, pitches 36/136).
// C = alpha*(A@W + bias).
// OUT: 0=fp32 natural, 1=fp16 natural (half2), 2=fp16 V^T.
// ---------------------------------------------------------------------------
#define GA_P 36
#define GB_P 136
#define GEMM_STAGE_A (128 * GA_P)
#define GEMM_STAGE_B (32 * GB_P)
#define GEMM_SMEM ((2 * (GEMM_STAGE_A + GEMM_STAGE_B)) * 4)

template<int OUT>
__global__ __launch_bounds__(256)
void gemm_tf32(const uint32_t* __restrict__ A,
               const uint32_t* __restrict__ W,
               const float* __restrict__ bias,
               void* __restrict__ Cout,
               float alpha)
{
    extern __shared__ uint32_t sg[];
    uint32_t* Asm = sg;                        // [2][128][GA_P]
    uint32_t* Bsm = sg + 2 * GEMM_STAGE_A;     // [2][32][GB_P]

    const int tid  = threadIdx.x;
    const int lane = tid & 31;
    const int gid  = lane >> 2;
    const int tg   = lane & 3;
    const int wid  = tid >> 5;
    const int warp_m = wid & 1;
    const int warp_n = wid >> 1;
    const int m0 = blockIdx.y * 128;
    const int n0 = blockIdx.x * 128;

    float c[4][4][4];
    #pragma unroll
    for (int mt = 0; mt < 4; mt++)
        #pragma unroll
        for (int nt = 0; nt < 4; nt++)
            #pragma unroll
            for (int i = 0; i < 4; i++) c[mt][nt][i] = 0.f;

    #pragma unroll
    for (int i = 0; i < 4; i++) {
        int idx = tid + i * 256;
        int row = idx >> 3, kk = (idx & 7) * 4;
        cpasync16(smem_u32(&Asm[row * GA_P + kk]),
                  &A[(size_t)(m0 + row) * D_MODEL + kk]);
    }
    #pragma unroll
    for (int i = 0; i < 4; i++) {
        int idx = tid + i * 256;
        int kk = idx >> 5, col = (idx & 31) * 4;
        cpasync16(smem_u32(&Bsm[kk * GB_P + col]),
                  &W[(size_t)kk * D_MODEL + n0 + col]);
    }
    cpasync_commit();

    int st = 0;
    for (int k0 = 0; k0 < D_MODEL; k0 += 32) {
        cpasync_wait<0>();
        __syncthreads();

        if (k0 + 32 < D_MODEL) {
            uint32_t* Ad = Asm + (st ^ 1) * GEMM_STAGE_A;
            uint32_t* Bd = Bsm + (st ^ 1) * GEMM_STAGE_B;
            #pragma unroll
            for (int i = 0; i < 4; i++) {
                int idx = tid + i * 256;
                int row = idx >> 3, kk = (idx & 7) * 4;
                cpasync16(smem_u32(&Ad[row * GA_P + kk]),
                          &A[(size_t)(m0 + row) * D_MODEL + k0 + 32 + kk]);
            }
            #pragma unroll
            for (int i = 0; i < 4; i++) {
                int idx = tid + i * 256;
                int kk = idx >> 5, col = (idx & 31) * 4;
                cpasync16(smem_u32(&Bd[kk * GB_P + col]),
                          &W[(size_t)(k0 + 32 + kk) * D_MODEL + n0 + col]);
            }
            cpasync_commit();
        }

        const uint32_t* As = Asm + st * GEMM_STAGE_A;
        const uint32_t* Bq = Bsm + st * GEMM_STAGE_B;

        #pragma unroll
        for (int ks = 0; ks < 32; ks += 8) {
            uint32_t af[4][4], bf[4][2];
            #pragma unroll
            for (int mt = 0; mt < 4; mt++) {
                int r = warp_m * 64 + mt * 16;
                af[mt][0] = As[(r + gid    ) * GA_P + ks + tg];
                af[mt][1] = As[(r + gid + 8) * GA_P + ks + tg];
                af[mt][2] = As[(r + gid    ) * GA_P + ks + tg + 4];
                af[mt][3] = As[(r + gid + 8) * GA_P + ks + tg + 4];
            }
            #pragma unroll
            for (int nt = 0; nt < 4; nt++) {
                int cb = warp_n * 32 + nt * 8;
                bf[nt][0] = Bq[(ks + tg    ) * GB_P + cb + gid];
                bf[nt][1] = Bq[(ks + tg + 4) * GB_P + cb + gid];
            }
            #pragma unroll
            for (int mt = 0; mt < 4; mt++)
                #pragma unroll
                for (int nt = 0; nt < 4; nt++)
                    mma_tf32(c[mt][nt], af[mt][0], af[mt][1], af[mt][2], af[mt][3],
                             bf[nt][0], bf[nt][1]);
        }
        st ^= 1;
    }

    #pragma unroll
    for (int mt = 0; mt < 4; mt++) {
        int r0 = m0 + warp_m * 64 + mt * 16 + gid;
        #pragma unroll
        for (int nt = 0; nt < 4; nt++) {
            int col = n0 + warp_n * 32 + nt * 8 + tg * 2;
            float2 bb = *(const float2*)&bias[col];
            float v00 = alpha * (c[mt][nt][0] + bb.x);
            float v01 = alpha * (c[mt][nt][1] + bb.y);
            float v10 = alpha * (c[mt][nt][2] + bb.x);
            float v11 = alpha * (c[mt][nt][3] + bb.y);
            if (OUT == 0) {
                float* C = (float*)Cout;
                *(float2*)&C[(size_t)r0 * D_MODEL + col] = make_float2(v00, v01);
                *(float2*)&C[(size_t)(r0 + 8) * D_MODEL + col] = make_float2(v10, v11);
            } else if (OUT == 1) {
                // fp16 natural: u32 row length = 512
                uint32_t* C = (uint32_t*)Cout;
                C[(size_t)r0 * 512 + (col >> 1)]       = pack_h2(v00, v01);
                C[(size_t)(r0 + 8) * 512 + (col >> 1)] = pack_h2(v10, v11);
            } else {
                // fp16 V^T: VT[(bi*16+h)*64+d][2048 halves]
                __half* VT = (__half*)Cout;
                int bi = r0 >> 11, tok = r0 & 2047;
                int h = col >> 6, d = col & 63;
                size_t row0 = ((size_t)(bi * 16 + h) * 64 + d) * 2048;
                size_t row1 = row0 + 2048;   // d+1
                VT[row0 + tok]     = __float2half_rn(v00);
                VT[row1 + tok]     = __float2half_rn(v01);
                VT[row0 + tok + 8] = __float2half_rn(v10);
                VT[row1 + tok + 8] = __float2half_rn(v11);
            }
        }
    }
}

// ---------------------------------------------------------------------------
// FP16 flash attention. Round-4 structure; each u32 = 2 halves, mma m16n8k16.
// CTA = 128 q rows x (b,h). 8 warps x 16 rows. Q fp16 in regs; K fp16 natural,
// V fp16 transposed; 2-stage cp.async (K,V same group). P via smem fp16.
// Output written as tf32 bits (natural) for the final tf32 GEMM.
// Pitch 36 u32 -> all scalar frag LDS conflict-free. smem = 55296 B.
// ---------------------------------------------------------------------------
#define AKP 36
#define AK_ST (64 * AKP)
#define AV_ST (64 * AKP)
#define AP_SZ (128 * AKP)
#define ATTN_SMEM ((2 * AK_ST + 2 * AV_ST + AP_SZ) * 4)

__global__ __launch_bounds__(256)
void attn_f16(const uint32_t* __restrict__ Q,
              const uint32_t* __restrict__ K,
              const uint32_t* __restrict__ V,
              uint32_t* __restrict__ O)
{
    extern __shared__ uint32_t sa[];
    uint32_t* Kbuf = sa;                        // [2][64][AKP]
    uint32_t* Vbuf = sa + 2 * AK_ST;            // [2][64][AKP]
    uint32_t* Ps   = sa + 2 * AK_ST + 2 * AV_ST; // [128][AKP]

    const int tid  = threadIdx.x;
    const int lane = tid & 31;
    const int wid  = tid >> 5;
    const int gid  = lane >> 2;
    const int tg   = lane & 3;
    const int rb   = wid * 16;

    const int q0 = blockIdx.x * 128;
    const int h  = blockIdx.y;
    const int b  = blockIdx.z;

    // u32 row length for fp16 natural = 512; head offset = h*32 u32
    const uint32_t* Qb  = Q + (size_t)b * SEQ * 512 + h * 32;
    const uint32_t* Kb  = K + (size_t)b * SEQ * 512 + h * 32;
    const uint32_t* Vtb = V + ((size_t)(b * 16 + h) * 64) * 1024;  // V^T rows: 1024 u32

    // Q fragments: 4 k-steps (16 halves each = 8 u32)
    uint32_t qf[4][4];
    {
        const uint32_t* qr0 = Qb + (size_t)(q0 + rb + gid) * 512;
        const uint32_t* qr1 = qr0 + (size_t)8 * 512;
        #pragma unroll
        for (int ks = 0; ks < 4; ks++) {
            qf[ks][0] = qr0[ks * 8 + tg    ];
            qf[ks][1] = qr1[ks * 8 + tg    ];
            qf[ks][2] = qr0[ks * 8 + tg + 4];
            qf[ks][3] = qr1[ks * 8 + tg + 4];
        }
    }

    // Prologue: K0 + V0 (each tile: 64 rows x 32 u32 = 512 x 16B chunks; 2/thread)
    #pragma unroll
    for (int i = 0; i < 2; i++) {
        int idx = tid + i * 256;
        int r = idx >> 3, ch = (idx & 7) * 4;
        cpasync16(smem_u32(&Kbuf[r * AKP + ch]), &Kb[(size_t)r * 512 + ch]);
        cpasync16(smem_u32(&Vbuf[r * AKP + ch]), &Vtb[(size_t)r * 1024 + ch]);
    }
    cpasync_commit();

    float o[8][4];
    #pragma unroll
    for (int nt = 0; nt < 8; nt++)
        #pragma unroll
        for (int i = 0; i < 4; i++) o[nt][i] = 0.f;
    float m_i[2] = { -1e30f, -1e30f };
    float l_i[2] = { 0.f, 0.f };

    int st = 0;
    for (int kt = 0; kt < SEQ; kt += 64) {
        cpasync_wait<0>();
        __syncthreads();

        if (kt + 64 < SEQ) {
            uint32_t* Kd = Kbuf + (st ^ 1) * AK_ST;
            uint32_t* Vd = Vbuf + (st ^ 1) * AV_ST;
            #pragma unroll
            for (int i = 0; i < 2; i++) {
                int idx = tid + i * 256;
                int r = idx >> 3, ch = (idx & 7) * 4;
                cpasync16(smem_u32(&Kd[r * AKP + ch]),
                          &Kb[(size_t)(kt + 64 + r) * 512 + ch]);
                cpasync16(smem_u32(&Vd[r * AKP + ch]),
                          &Vtb[(size_t)r * 1024 + (kt + 64) / 2 + ch]);
            }
            cpasync_commit();
        }

        const uint32_t* Ks = Kbuf + st * AK_ST;
        const uint32_t* Vs = Vbuf + st * AV_ST;

        // S = Q @ K^T  (4 k-steps of 16)
        float s[8][4];
        #pragma unroll
        for (int nt = 0; nt < 8; nt++)
            #pragma unroll
            for (int i = 0; i < 4; i++) s[nt][i] = 0.f;

        #pragma unroll
        for (int ks = 0; ks < 4; ks++) {
            #pragma unroll
            for (int nt = 0; nt < 8; nt++) {
                uint32_t b0 = Ks[(nt * 8 + gid) * AKP + ks * 8 + tg];
                uint32_t b1 = Ks[(nt * 8 + gid) * AKP + ks * 8 + tg + 4];
                mma_f16(s[nt], qf[ks][0], qf[ks][1], qf[ks][2], qf[ks][3], b0, b1);
            }
        }

        // Online softmax (rows rb+gid, rb+gid+8; quad reduce)
        #pragma unroll
        for (int half = 0; half < 2; half++) {
            float mx = -1e30f;
            #pragma unroll
            for (int nt = 0; nt < 8; nt++)
                mx = fmaxf(mx, fmaxf(s[nt][half * 2], s[nt][half * 2 + 1]));
            mx = fmaxf(mx, __shfl_xor_sync(0xffffffffu, mx, 1));
            mx = fmaxf(mx, __shfl_xor_sync(0xffffffffu, mx, 2));

            float mnew = fmaxf(m_i[half], mx);
            float corr = __expf(m_i[half] - mnew);
            float rs = 0.f;
            #pragma unroll
            for (int nt = 0; nt < 8; nt++) {
                s[nt][half * 2]     = __expf(s[nt][half * 2]     - mnew);
                s[nt][half * 2 + 1] = __expf(s[nt][half * 2 + 1] - mnew);
                rs += s[nt][half * 2] + s[nt][half * 2 + 1];
            }
            rs += __shfl_xor_sync(0xffffffffu, rs, 1);
            rs += __shfl_xor_sync(0xffffffffu, rs, 2);

            l_i[half] = l_i[half] * corr + rs;
            m_i[half] = mnew;
            #pragma unroll
            for (int nt = 0; nt < 8; nt++) {
                o[nt][half * 2]     *= corr;
                o[nt][half * 2 + 1] *= corr;
            }
        }

        // P -> smem fp16 (warp-private rows). cols nt*8+tg*2(,+1) -> u32 nt*4+tg
        __syncwarp();
        #pragma unroll
        for (int nt = 0; nt < 8; nt++) {
            Ps[(rb + gid    ) * AKP + nt * 4 + tg] = pack_h2(s[nt][0], s[nt][1]);
            Ps[(rb + gid + 8) * AKP + nt * 4 + tg] = pack_h2(s[nt][2], s[nt][3]);
        }
        __syncwarp();

        // O += P @ V  (V^T rows = d, cols = keys)
        #pragma unroll
        for (int ks = 0; ks < 4; ks++) {
            uint32_t a0 = Ps[(rb + gid    ) * AKP + ks * 8 + tg];
            uint32_t a1 = Ps[(rb + gid + 8) * AKP + ks * 8 + tg];
            uint32_t a2 = Ps[(rb + gid    ) * AKP + ks * 8 + tg + 4];
            uint32_t a3 = Ps[(rb + gid + 8) * AKP + ks * 8 + tg + 4];
            #pragma unroll
            for (int nt = 0; nt < 8; nt++) {
                uint32_t b0 = Vs[(nt * 8 + gid) * AKP + ks * 8 + tg];
                uint32_t b1 = Vs[(nt * 8 + gid) * AKP + ks * 8 + tg + 4];
                mma_f16(o[nt], a0, a1, a2, a3, b0, b1);
            }
        }
        st ^= 1;
    }

    // Epilogue: normalize, write NATURAL tf32 (round-4 form) for final GEMM
    float inv0 = 1.0f / l_i[0];
    float inv1 = 1.0f / l_i[1];
    uint32_t* Ob = O + (size_t)b * SEQ * D_MODEL + h * D_K;
    int r0 = q0 + rb + gid;
    #pragma unroll
    for (int nt = 0; nt < 8; nt++) {
        int col = nt * 8 + tg * 2;
        uint2 t0 = { f2tf32(o[nt][0] * inv0), f2tf32(o[nt][1] * inv0) };
        *(uint2*)&Ob[(size_t)r0 * D_MODEL + col] = t0;
        uint2 t1 = { f2tf32(o[nt][2] * inv1), f2tf32(o[nt][3] * inv1) };
        *(uint2*)&Ob[(size_t)(r0 + 8) * D_MODEL + col] = t1;
    }
}

// ---------------------------------------------------------------------------
// kernel_launch — inputs: q, k, v, w_q, b_q, w_k, b_k, w_v, b_v, w_o, b_o
// ---------------------------------------------------------------------------
extern "C" void kernel_launch(void* const* d_in, const int* in_sizes, int n_in,
                              void* d_out, int out_size)
{
    const float* q   = (const float*)d_in[0];
    const float* k   = (const float*)d_in[1];
    const float* v   = (const float*)d_in[2];
    const float* w_q = (const float*)d_in[3];
    const float* b_q = (const float*)d_in[4];
    const float* w_k = (const float*)d_in[5];
    const float* b_k = (const float*)d_in[6];
    const float* w_v = (const float*)d_in[7];
    const float* b_v = (const float*)d_in[8];
    const float* w_o = (const float*)d_in[9];
    const float* b_o = (const float*)d_in[10];
    float* out = (float*)d_out;

    uint32_t *tq, *tk, *tv, *twq, *twk, *twv, *two, *gq, *gk, *gv, *go;
    cudaGetSymbolAddress((void**)&tq,  t_q);
    cudaGetSymbolAddress((void**)&tk,  t_k);
    cudaGetSymbolAddress((void**)&tv,  t_v);
    cudaGetSymbolAddress((void**)&twq, t_wq);
    cudaGetSymbolAddress((void**)&twk, t_wk);
    cudaGetSymbolAddress((void**)&twv, t_wv);
    cudaGetSymbolAddress((void**)&two, t_wo);
    cudaGetSymbolAddress((void**)&gq,  g_Q);
    cudaGetSymbolAddress((void**)&gk,  g_K);
    cudaGetSymbolAddress((void**)&gv,  g_V);
    cudaGetSymbolAddress((void**)&go,  g_O);

    cudaFuncSetAttribute(gemm_tf32<0>, cudaFuncAttributeMaxDynamicSharedMemorySize, GEMM_SMEM);
    cudaFuncSetAttribute(gemm_tf32<1>, cudaFuncAttributeMaxDynamicSharedMemorySize, GEMM_SMEM);
    cudaFuncSetAttribute(gemm_tf32<2>, cudaFuncAttributeMaxDynamicSharedMemorySize, GEMM_SMEM);
    cudaFuncSetAttribute(attn_f16,     cudaFuncAttributeMaxDynamicSharedMemorySize, ATTN_SMEM);

    // Pre-pass (2 launches): cvt to tf32, natural layouts
    const int n4_act = M_ROWS * D_MODEL / 4;
    const int n4_w   = D_MODEL * D_MODEL / 4;
    dim3 act_grid(n4_act / 256, 3);
    cvt3_kernel<<<act_grid, 256>>>((const float4*)q, (const float4*)k, (const float4*)v,
                                   (uint4*)tq, (uint4*)tk, (uint4*)tv, n4_act);
    dim3 w_grid(n4_w / 256, 4);
    cvt4_kernel<<<w_grid, 256>>>((const float4*)w_q, (const float4*)w_k,
                                 (const float4*)w_v, (const float4*)w_o,
                                 (uint4*)twq, (uint4*)twk, (uint4*)twv, (uint4*)two, n4_w);

    dim3 gemm_grid(D_MODEL / 128, M_ROWS / 128);  // (8, 32)
    gemm_tf32<1><<<gemm_grid, 256, GEMM_SMEM>>>(tq, twq, b_q, gq, 0.125f);  // Q fp16
    gemm_tf32<1><<<gemm_grid, 256, GEMM_SMEM>>>(tk, twk, b_k, gk, 1.0f);    // K fp16
    gemm_tf32<2><<<gemm_grid, 256, GEMM_SMEM>>>(tv, twv, b_v, gv, 1.0f);    // V^T fp16

    dim3 attn_grid(SEQ / 128, N_HEADS, BATCH);    // (16, 16, 2)
    attn_f16<<<attn_grid, 256, ATTN_SMEM>>>(gq, gk, gv, go);

    gemm_tf32<0><<<gemm_grid, 256, GEMM_SMEM>>>(go, two, b_o, out, 1.0f);
}

// round 12
// speedup vs baseline: 2.0554x; 1.3340x over previous
#include <cuda_runtime.h>
#include <cuda_fp16.h>
#include <cstdint>

#define D_MODEL 1024
#define N_HEADS 16
#define D_K     64
#define BATCH   2
#define SEQ     2048
#define M_ROWS  (BATCH * SEQ)   // 4096

// Scratch (allocation-free rule: __device__ globals).
__device__ uint32_t t_q [M_ROWS * D_MODEL / 2];   // fp16 natural acts [m][512 u32]
__device__ uint32_t t_k [M_ROWS * D_MODEL / 2];
__device__ uint32_t t_v [M_ROWS * D_MODEL / 2];
__device__ uint32_t t_wq[D_MODEL * D_MODEL / 2];  // fp16 TRANSPOSED weights Wt[n][512 u32]
__device__ uint32_t t_wk[D_MODEL * D_MODEL / 2];
__device__ uint32_t t_wv[D_MODEL * D_MODEL / 2];
__device__ uint32_t t_wo[D_MODEL * D_MODEL / 2];
__device__ uint32_t g_Q [M_ROWS * D_MODEL / 2];   // fp16 natural, pre-scaled
__device__ uint32_t g_K [M_ROWS * D_MODEL / 2];   // fp16 natural
__device__ uint32_t g_V [M_ROWS * D_MODEL / 2];   // fp16 V^T: [(b*16+h)*64+d][2048 halves]
__device__ uint32_t g_O [M_ROWS * D_MODEL / 2];   // fp16 natural (attn out)

__device__ __forceinline__ uint32_t pack_h2(float lo, float hi) {
    __half2 h = __floats2half2_rn(lo, hi);   // .x = lo (low 16 bits)
    return *(uint32_t*)&h;
}

__device__ __forceinline__ void mma_f16(float c[4],
                                        uint32_t a0, uint32_t a1, uint32_t a2, uint32_t a3,
                                        uint32_t b0, uint32_t b1) {
    asm volatile(
        "mma.sync.aligned.m16n8k16.row.col.f32.f16.f16.f32 "
        "{%0,%1,%2,%3}, {%4,%5,%6,%7}, {%8,%9}, {%0,%1,%2,%3};"
        : "+f"(c[0]), "+f"(c[1]), "+f"(c[2]), "+f"(c[3])
        : "r"(a0), "r"(a1), "r"(a2), "r"(a3), "r"(b0), "r"(b1));
}

__device__ __forceinline__ uint32_t smem_u32(const void* p) {
    return (uint32_t)__cvta_generic_to_shared(p);
}
__device__ __forceinline__ void cpasync16(uint32_t dst, const void* src) {
    asm volatile("cp.async.cg.shared.global [%0], [%1], 16;" :: "r"(dst), "l"(src));
}
__device__ __forceinline__ void cpasync_commit() {
    asm volatile("cp.async.commit_group;");
}
template<int N> __device__ __forceinline__ void cpasync_wait() {
    asm volatile("cp.async.wait_group %0;" :: "n"(N));
}

// ---------------------------------------------------------------------------
// Pre-pass 1: fp32 -> fp16 natural acts (fused q/k/v).
// ---------------------------------------------------------------------------
__global__ __launch_bounds__(256)
void cvt3_kernel(const float4* __restrict__ q, const float4* __restrict__ k,
                 const float4* __restrict__ v,
                 uint2* __restrict__ tq, uint2* __restrict__ tk,
                 uint2* __restrict__ tv, int n4)
{
    int i = blockIdx.x * 256 + threadIdx.x;
    if (i >= n4) return;
    const float4* in = (blockIdx.y == 0) ? q : (blockIdx.y == 1) ? k : v;
    uint2*       out = (blockIdx.y == 0) ? tq : (blockIdx.y == 1) ? tk : tv;
    float4 a = in[i];
    uint2 u = { pack_h2(a.x, a.y), pack_h2(a.z, a.w) };
    out[i] = u;
}

// ---------------------------------------------------------------------------
// Pre-pass 2: transpose + cvt all 4 weights: W[k][n] fp32 -> Wt[n][k] fp16.
// ---------------------------------------------------------------------------
__global__ __launch_bounds__(256)
void wT4_kernel(const float* __restrict__ wq, const float* __restrict__ wk,
                const float* __restrict__ wv, const float* __restrict__ wo,
                __half* __restrict__ twq, __half* __restrict__ twk,
                __half* __restrict__ twv, __half* __restrict__ two)
{
    __shared__ float ts[32][33];
    const float* W  = (blockIdx.z == 0) ? wq  : (blockIdx.z == 1) ? wk  :
                      (blockIdx.z == 2) ? wv  : wo;
    __half*      Wt = (blockIdx.z == 0) ? twq : (blockIdx.z == 1) ? twk :
                      (blockIdx.z == 2) ? twv : two;
    int k0 = blockIdx.x * 32, n0 = blockIdx.y * 32;
    int tx = threadIdx.x, ty = threadIdx.y;
    #pragma unroll
    for (int r = 0; r < 4; r++)
        ts[ty + r * 8][tx] = W[(size_t)(k0 + ty + r * 8) * 1024 + n0 + tx];
    __syncthreads();
    #pragma unroll
    for (int r = 0; r < 4; r++) {
        int n = ty + r * 8;
        Wt[(size_t)(n0 + n) * 1024 + k0 + tx] = __float2half_rn(ts[tx][n]);
    }
}

// ---------------------------------------------------------------------------
// FP16 GEMM: C = alpha*(A@W + bias). A fp16 natural [m][512u32];
// Wt fp16 transposed [n][512u32]. BM=BN=128, BK=64 (32 u32), 2-stage
// cp.async, 256 thr, warp tile 64x32, pitch 36. 16 mainloop iterations.
// Fragment indexing identical to the (verified) attn_f16 patterns.
// OUT: 0=fp32 natural, 1=fp16 natural, 2=fp16 V^T.
// ---------------------------------------------------------------------------
#define GP 36
#define GST (128 * GP)
#define GEMM_SMEM ((4 * GST) * 4)     // 2 stages x (A+B), 73728 B

template<int OUT>
__global__ __launch_bounds__(256)
void gemm_f16(const uint32_t* __restrict__ A,
              const uint32_t* __restrict__ Wt,
              const float* __restrict__ bias,
              void* __restrict__ Cout,
              float alpha)
{
    extern __shared__ uint32_t sg[];
    uint32_t* Asm = sg;               // [2][128][GP]
    uint32_t* Bsm = sg + 2 * GST;     // [2][128][GP]

    const int tid  = threadIdx.x;
    const int lane = tid & 31;
    const int gid  = lane >> 2;
    const int tg   = lane & 3;
    const int wid  = tid >> 5;
    const int warp_m = wid & 1;
    const int warp_n = wid >> 1;
    const int m0 = blockIdx.y * 128;
    const int n0 = blockIdx.x * 128;

    float c[4][4][4];
    #pragma unroll
    for (int mt = 0; mt < 4; mt++)
        #pragma unroll
        for (int nt = 0; nt < 4; nt++)
            #pragma unroll
            for (int i = 0; i < 4; i++) c[mt][nt][i] = 0.f;

    // Prologue: stage 0. Tiles: 128 rows x 32 u32 = 1024 x 16B chunks; 4/thread each.
    #pragma unroll
    for (int i = 0; i < 4; i++) {
        int idx = tid + i * 256;
        int row = idx >> 3, ch = (idx & 7) * 4;
        cpasync16(smem_u32(&Asm[row * GP + ch]), &A [(size_t)(m0 + row) * 512 + ch]);
        cpasync16(smem_u32(&Bsm[row * GP + ch]), &Wt[(size_t)(n0 + row) * 512 + ch]);
    }
    cpasync_commit();

    int st = 0;
    for (int k0 = 0; k0 < 512; k0 += 32) {      // k in u32 units; BK=64 halves
        cpasync_wait<0>();
        __syncthreads();

        if (k0 + 32 < 512) {
            uint32_t* Ad = Asm + (st ^ 1) * GST;
            uint32_t* Bd = Bsm + (st ^ 1) * GST;
            #pragma unroll
            for (int i = 0; i < 4; i++) {
                int idx = tid + i * 256;
                int row = idx >> 3, ch = (idx & 7) * 4;
                cpasync16(smem_u32(&Ad[row * GP + ch]),
                          &A [(size_t)(m0 + row) * 512 + k0 + 32 + ch]);
                cpasync16(smem_u32(&Bd[row * GP + ch]),
                          &Wt[(size_t)(n0 + row) * 512 + k0 + 32 + ch]);
            }
            cpasync_commit();
        }

        const uint32_t* As = Asm + st * GST;
        const uint32_t* Bs = Bsm + st * GST;

        #pragma unroll
        for (int ks = 0; ks < 4; ks++) {        // 4 k-steps of 16 halves
            uint32_t af[4][4], bf[4][2];
            #pragma unroll
            for (int mt = 0; mt < 4; mt++) {
                int r = warp_m * 64 + mt * 16;
                af[mt][0] = As[(r + gid    ) * GP + ks * 8 + tg];
                af[mt][1] = As[(r + gid + 8) * GP + ks * 8 + tg];
                af[mt][2] = As[(r + gid    ) * GP + ks * 8 + tg + 4];
                af[mt][3] = As[(r + gid + 8) * GP + ks * 8 + tg + 4];
            }
            #pragma unroll
            for (int nt = 0; nt < 4; nt++) {
                int rn = warp_n * 32 + nt * 8 + gid;
                bf[nt][0] = Bs[rn * GP + ks * 8 + tg];
                bf[nt][1] = Bs[rn * GP + ks * 8 + tg + 4];
            }
            #pragma unroll
            for (int mt = 0; mt < 4; mt++)
                #pragma unroll
                for (int nt = 0; nt < 4; nt++)
                    mma_f16(c[mt][nt], af[mt][0], af[mt][1], af[mt][2], af[mt][3],
                            bf[nt][0], bf[nt][1]);
        }
        st ^= 1;
    }

    #pragma unroll
    for (int mt = 0; mt < 4; mt++) {
        int r0 = m0 + warp_m * 64 + mt * 16 + gid;
        #pragma unroll
        for (int nt = 0; nt < 4; nt++) {
            int col = n0 + warp_n * 32 + nt * 8 + tg * 2;
            float2 bb = *(const float2*)&bias[col];
            float v00 = alpha * (c[mt][nt][0] + bb.x);
            float v01 = alpha * (c[mt][nt][1] + bb.y);
            float v10 = alpha * (c[mt][nt][2] + bb.x);
            float v11 = alpha * (c[mt][nt][3] + bb.y);
            if (OUT == 0) {
                float* C = (float*)Cout;
                *(float2*)&C[(size_t)r0 * D_MODEL + col] = make_float2(v00, v01);
                *(float2*)&C[(size_t)(r0 + 8) * D_MODEL + col] = make_float2(v10, v11);
            } else if (OUT == 1) {
                uint32_t* C = (uint32_t*)Cout;
                C[(size_t)r0 * 512 + (col >> 1)]       = pack_h2(v00, v01);
                C[(size_t)(r0 + 8) * 512 + (col >> 1)] = pack_h2(v10, v11);
            } else {
                // fp16 V^T: VT[(bi*16+h)*64+d][2048 halves]
                __half* VT = (__half*)Cout;
                int bi = r0 >> 11, tok = r0 & 2047;
                int h = col >> 6, d = col & 63;
                size_t row0 = ((size_t)(bi * 16 + h) * 64 + d) * 2048;
                size_t row1 = row0 + 2048;   // d+1
                VT[row0 + tok]     = __float2half_rn(v00);
                VT[row1 + tok]     = __float2half_rn(v01);
                VT[row0 + tok + 8] = __float2half_rn(v10);
                VT[row1 + tok + 8] = __float2half_rn(v11);
            }
        }
    }
}

// ---------------------------------------------------------------------------
// FP16 flash attention — round-11 passing version; epilogue now writes fp16
// natural O (half2) for the fp16 final GEMM. smem = 55296 B.
// ---------------------------------------------------------------------------
#define AKP 36
#define AK_ST (64 * AKP)
#define AV_ST (64 * AKP)
#define AP_SZ (128 * AKP)
#define ATTN_SMEM ((2 * AK_ST + 2 * AV_ST + AP_SZ) * 4)

__global__ __launch_bounds__(256)
void attn_f16(const uint32_t* __restrict__ Q,
              const uint32_t* __restrict__ K,
              const uint32_t* __restrict__ V,
              uint32_t* __restrict__ O)
{
    extern __shared__ uint32_t sa[];
    uint32_t* Kbuf = sa;                        // [2][64][AKP]
    uint32_t* Vbuf = sa + 2 * AK_ST;            // [2][64][AKP]
    uint32_t* Ps   = sa + 2 * AK_ST + 2 * AV_ST; // [128][AKP]

    const int tid  = threadIdx.x;
    const int lane = tid & 31;
    const int wid  = tid >> 5;
    const int gid  = lane >> 2;
    const int tg   = lane & 3;
    const int rb   = wid * 16;

    const int q0 = blockIdx.x * 128;
    const int h  = blockIdx.y;
    const int b  = blockIdx.z;

    const uint32_t* Qb  = Q + (size_t)b * SEQ * 512 + h * 32;
    const uint32_t* Kb  = K + (size_t)b * SEQ * 512 + h * 32;
    const uint32_t* Vtb = V + ((size_t)(b * 16 + h) * 64) * 1024;

    uint32_t qf[4][4];
    {
        const uint32_t* qr0 = Qb + (size_t)(q0 + rb + gid) * 512;
        const uint32_t* qr1 = qr0 + (size_t)8 * 512;
        #pragma unroll
        for (int ks = 0; ks < 4; ks++) {
            qf[ks][0] = qr0[ks * 8 + tg    ];
            qf[ks][1] = qr1[ks * 8 + tg    ];
            qf[ks][2] = qr0[ks * 8 + tg + 4];
            qf[ks][3] = qr1[ks * 8 + tg + 4];
        }
    }

    #pragma unroll
    for (int i = 0; i < 2; i++) {
        int idx = tid + i * 256;
        int r = idx >> 3, ch = (idx & 7) * 4;
        cpasync16(smem_u32(&Kbuf[r * AKP + ch]), &Kb[(size_t)r * 512 + ch]);
        cpasync16(smem_u32(&Vbuf[r * AKP + ch]), &Vtb[(size_t)r * 1024 + ch]);
    }
    cpasync_commit();

    float o[8][4];
    #pragma unroll
    for (int nt = 0; nt < 8; nt++)
        #pragma unroll
        for (int i = 0; i < 4; i++) o[nt][i] = 0.f;
    float m_i[2] = { -1e30f, -1e30f };
    float l_i[2] = { 0.f, 0.f };

    int st = 0;
    for (int kt = 0; kt < SEQ; kt += 64) {
        cpasync_wait<0>();
        __syncthreads();

        if (kt + 64 < SEQ) {
            uint32_t* Kd = Kbuf + (st ^ 1) * AK_ST;
            uint32_t* Vd = Vbuf + (st ^ 1) * AV_ST;
            #pragma unroll
            for (int i = 0; i < 2; i++) {
                int idx = tid + i * 256;
                int r = idx >> 3, ch = (idx & 7) * 4;
                cpasync16(smem_u32(&Kd[r * AKP + ch]),
                          &Kb[(size_t)(kt + 64 + r) * 512 + ch]);
                cpasync16(smem_u32(&Vd[r * AKP + ch]),
                          &Vtb[(size_t)r * 1024 + (kt + 64) / 2 + ch]);
            }
            cpasync_commit();
        }

        const uint32_t* Ks = Kbuf + st * AK_ST;
        const uint32_t* Vs = Vbuf + st * AV_ST;

        float s[8][4];
        #pragma unroll
        for (int nt = 0; nt < 8; nt++)
            #pragma unroll
            for (int i = 0; i < 4; i++) s[nt][i] = 0.f;

        #pragma unroll
        for (int ks = 0; ks < 4; ks++) {
            #pragma unroll
            for (int nt = 0; nt < 8; nt++) {
                uint32_t b0 = Ks[(nt * 8 + gid) * AKP + ks * 8 + tg];
                uint32_t b1 = Ks[(nt * 8 + gid) * AKP + ks * 8 + tg + 4];
                mma_f16(s[nt], qf[ks][0], qf[ks][1], qf[ks][2], qf[ks][3], b0, b1);
            }
        }

        #pragma unroll
        for (int half = 0; half < 2; half++) {
            float mx = -1e30f;
            #pragma unroll
            for (int nt = 0; nt < 8; nt++)
                mx = fmaxf(mx, fmaxf(s[nt][half * 2], s[nt][half * 2 + 1]));
            mx = fmaxf(mx, __shfl_xor_sync(0xffffffffu, mx, 1));
            mx = fmaxf(mx, __shfl_xor_sync(0xffffffffu, mx, 2));

            float mnew = fmaxf(m_i[half], mx);
            float corr = __expf(m_i[half] - mnew);
            float rs = 0.f;
            #pragma unroll
            for (int nt = 0; nt < 8; nt++) {
                s[nt][half * 2]     = __expf(s[nt][half * 2]     - mnew);
                s[nt][half * 2 + 1] = __expf(s[nt][half * 2 + 1] - mnew);
                rs += s[nt][half * 2] + s[nt][half * 2 + 1];
            }
            rs += __shfl_xor_sync(0xffffffffu, rs, 1);
            rs += __shfl_xor_sync(0xffffffffu, rs, 2);

            l_i[half] = l_i[half] * corr + rs;
            m_i[half] = mnew;
            #pragma unroll
            for (int nt = 0; nt < 8; nt++) {
                o[nt][half * 2]     *= corr;
                o[nt][half * 2 + 1] *= corr;
            }
        }

        __syncwarp();
        #pragma unroll
        for (int nt = 0; nt < 8; nt++) {
            Ps[(rb + gid    ) * AKP + nt * 4 + tg] = pack_h2(s[nt][0], s[nt][1]);
            Ps[(rb + gid + 8) * AKP + nt * 4 + tg] = pack_h2(s[nt][2], s[nt][3]);
        }
        __syncwarp();

        #pragma unroll
        for (int ks = 0; ks < 4; ks++) {
            uint32_t a0 = Ps[(rb + gid    ) * AKP + ks * 8 + tg];
            uint32_t a1 = Ps[(rb + gid + 8) * AKP + ks * 8 + tg];
            uint32_t a2 = Ps[(rb + gid    ) * AKP + ks * 8 + tg + 4];
            uint32_t a3 = Ps[(rb + gid + 8) * AKP + ks * 8 + tg + 4];
            #pragma unroll
            for (int nt = 0; nt < 8; nt++) {
                uint32_t b0 = Vs[(nt * 8 + gid) * AKP + ks * 8 + tg];
                uint32_t b1 = Vs[(nt * 8 + gid) * AKP + ks * 8 + tg + 4];
                mma_f16(o[nt], a0, a1, a2, a3, b0, b1);
            }
        }
        st ^= 1;
    }

    // Epilogue: normalize, write fp16 natural O for the fp16 final GEMM
    float inv0 = 1.0f / l_i[0];
    float inv1 = 1.0f / l_i[1];
    uint32_t* Ob = O + (size_t)b * SEQ * 512 + h * 32;
    int r0 = q0 + rb + gid;
    #pragma unroll
    for (int nt = 0; nt < 8; nt++) {
        int u = nt * 4 + tg;   // u32 index within head (= col/2)
        Ob[(size_t)r0 * 512 + u]       = pack_h2(o[nt][0] * inv0, o[nt][1] * inv0);
        Ob[(size_t)(r0 + 8) * 512 + u] = pack_h2(o[nt][2] * inv1, o[nt][3] * inv1);
    }
}

// ---------------------------------------------------------------------------
// kernel_launch — inputs: q, k, v, w_q, b_q, w_k, b_k, w_v, b_v, w_o, b_o
// ---------------------------------------------------------------------------
extern "C" void kernel_launch(void* const* d_in, const int* in_sizes, int n_in,
                              void* d_out, int out_size)
{
    const float* q   = (const float*)d_in[0];
    const float* k   = (const float*)d_in[1];
    const float* v   = (const float*)d_in[2];
    const float* w_q = (const float*)d_in[3];
    const float* b_q = (const float*)d_in[4];
    const float* w_k = (const float*)d_in[5];
    const float* b_k = (const float*)d_in[6];
    const float* w_v = (const float*)d_in[7];
    const float* b_v = (const float*)d_in[8];
    const float* w_o = (const float*)d_in[9];
    const float* b_o = (const float*)d_in[10];
    float* out = (float*)d_out;

    uint32_t *tq, *tk, *tv, *twq, *twk, *twv, *two, *gq, *gk, *gv, *go;
    cudaGetSymbolAddress((void**)&tq,  t_q);
    cudaGetSymbolAddress((void**)&tk,  t_k);
    cudaGetSymbolAddress((void**)&tv,  t_v);
    cudaGetSymbolAddress((void**)&twq, t_wq);
    cudaGetSymbolAddress((void**)&twk, t_wk);
    cudaGetSymbolAddress((void**)&twv, t_wv);
    cudaGetSymbolAddress((void**)&two, t_wo);
    cudaGetSymbolAddress((void**)&gq,  g_Q);
    cudaGetSymbolAddress((void**)&gk,  g_K);
    cudaGetSymbolAddress((void**)&gv,  g_V);
    cudaGetSymbolAddress((void**)&go,  g_O);

    cudaFuncSetAttribute(gemm_f16<0>, cudaFuncAttributeMaxDynamicSharedMemorySize, GEMM_SMEM);
    cudaFuncSetAttribute(gemm_f16<1>, cudaFuncAttributeMaxDynamicSharedMemorySize, GEMM_SMEM);
    cudaFuncSetAttribute(gemm_f16<2>, cudaFuncAttributeMaxDynamicSharedMemorySize, GEMM_SMEM);
    cudaFuncSetAttribute(attn_f16,    cudaFuncAttributeMaxDynamicSharedMemorySize, ATTN_SMEM);

    // Pre-pass (2 launches): cvt acts to fp16; transpose+cvt weights to fp16
    const int n4_act = M_ROWS * D_MODEL / 4;
    dim3 act_grid(n4_act / 256, 3);
    cvt3_kernel<<<act_grid, 256>>>((const float4*)q, (const float4*)k, (const float4*)v,
                                   (uint2*)tq, (uint2*)tk, (uint2*)tv, n4_act);
    dim3 wt_grid(32, 32, 4), wt_block(32, 8);
    wT4_kernel<<<wt_grid, wt_block>>>(w_q, w_k, w_v, w_o,
                                      (__half*)twq, (__half*)twk, (__half*)twv, (__half*)two);

    dim3 gemm_grid(D_MODEL / 128, M_ROWS / 128);  // (8, 32)
    gemm_f16<1><<<gemm_grid, 256, GEMM_SMEM>>>(tq, twq, b_q, gq, 0.125f);  // Q fp16 natural
    gemm_f16<1><<<gemm_grid, 256, GEMM_SMEM>>>(tk, twk, b_k, gk, 1.0f);    // K fp16 natural
    gemm_f16<2><<<gemm_grid, 256, GEMM_SMEM>>>(tv, twv, b_v, gv, 1.0f);    // V^T fp16

    dim3 attn_grid(SEQ / 128, N_HEADS, BATCH);    // (16, 16, 2)
    attn_f16<<<attn_grid, 256, ATTN_SMEM>>>(gq, gk, gv, go);

    gemm_f16<0><<<gemm_grid, 256, GEMM_SMEM>>>(go, two, b_o, out, 1.0f);
}

// round 13
// speedup vs baseline: 2.1993x; 1.0700x over previous
#include <cuda_runtime.h>
#include <cuda_fp16.h>
#include <cstdint>

#define D_MODEL 1024
#define N_HEADS 16
#define D_K     64
#define BATCH   2
#define SEQ     2048
#define M_ROWS  (BATCH * SEQ)   // 4096

// Scratch (allocation-free rule: __device__ globals).
__device__ uint32_t t_q [M_ROWS * D_MODEL / 2];   // fp16 natural acts [m][512 u32]
__device__ uint32_t t_k [M_ROWS * D_MODEL / 2];
__device__ uint32_t t_v [M_ROWS * D_MODEL / 2];
__device__ uint32_t t_wq[D_MODEL * D_MODEL / 2];  // fp16 TRANSPOSED weights Wt[n][512 u32]
__device__ uint32_t t_wk[D_MODEL * D_MODEL / 2];
__device__ uint32_t t_wv[D_MODEL * D_MODEL / 2];
__device__ uint32_t t_wo[D_MODEL * D_MODEL / 2];
__device__ uint32_t g_Q [M_ROWS * D_MODEL / 2];   // fp16 natural, pre-scaled
__device__ uint32_t g_K [M_ROWS * D_MODEL / 2];   // fp16 natural
__device__ uint32_t g_V [M_ROWS * D_MODEL / 2];   // fp16 V^T: [(b*16+h)*64+d][2048 halves]
__device__ uint32_t g_O [M_ROWS * D_MODEL / 2];   // fp16 natural (attn out)

__device__ __forceinline__ uint32_t pack_h2(float lo, float hi) {
    __half2 h = __floats2half2_rn(lo, hi);
    return *(uint32_t*)&h;
}

__device__ __forceinline__ void mma_f16(float c[4],
                                        uint32_t a0, uint32_t a1, uint32_t a2, uint32_t a3,
                                        uint32_t b0, uint32_t b1) {
    asm volatile(
        "mma.sync.aligned.m16n8k16.row.col.f32.f16.f16.f32 "
        "{%0,%1,%2,%3}, {%4,%5,%6,%7}, {%8,%9}, {%0,%1,%2,%3};"
        : "+f"(c[0]), "+f"(c[1]), "+f"(c[2]), "+f"(c[3])
        : "r"(a0), "r"(a1), "r"(a2), "r"(a3), "r"(b0), "r"(b1));
}

__device__ __forceinline__ void ldsm_x4(uint32_t& r0, uint32_t& r1,
                                        uint32_t& r2, uint32_t& r3, uint32_t addr) {
    asm volatile("ldmatrix.sync.aligned.m8n8.x4.shared.b16 {%0,%1,%2,%3}, [%4];"
                 : "=r"(r0), "=r"(r1), "=r"(r2), "=r"(r3) : "r"(addr));
}

__device__ __forceinline__ uint32_t smem_u32(const void* p) {
    return (uint32_t)__cvta_generic_to_shared(p);
}
__device__ __forceinline__ void cpasync16(uint32_t dst, const void* src) {
    asm volatile("cp.async.cg.shared.global [%0], [%1], 16;" :: "r"(dst), "l"(src));
}
__device__ __forceinline__ void cpasync_commit() {
    asm volatile("cp.async.commit_group;");
}
template<int N> __device__ __forceinline__ void cpasync_wait() {
    asm volatile("cp.async.wait_group %0;" :: "n"(N));
}

// ldmatrix per-lane offsets (u32 units) for pitch P:
// A/P-operand (16-row tile): tiles = [r+0..7 kc0][r+8..15 kc0][r+0..7 kc1][r+8..15 kc1]
__device__ __forceinline__ int ldsm_a_off(int lane, int P) {
    return ((lane & 7) + ((lane >> 3) & 1) * 8) * P + (lane >> 4) * 4;
}
// B-operand pair (two adjacent 8-row nt tiles): [nt kc0][nt kc1][nt+1 kc0][nt+1 kc1]
__device__ __forceinline__ int ldsm_b_off(int lane, int P) {
    return (lane & 7) * P + ((lane >> 3) & 1) * 4 + (lane >> 4) * 8 * P;
}

// ---------------------------------------------------------------------------
// Pre-pass 1: fp32 -> fp16 natural acts (fused q/k/v).
// ---------------------------------------------------------------------------
__global__ __launch_bounds__(256)
void cvt3_kernel(const float4* __restrict__ q, const float4* __restrict__ k,
                 const float4* __restrict__ v,
                 uint2* __restrict__ tq, uint2* __restrict__ tk,
                 uint2* __restrict__ tv, int n4)
{
    int i = blockIdx.x * 256 + threadIdx.x;
    if (i >= n4) return;
    const float4* in = (blockIdx.y == 0) ? q : (blockIdx.y == 1) ? k : v;
    uint2*       out = (blockIdx.y == 0) ? tq : (blockIdx.y == 1) ? tk : tv;
    float4 a = in[i];
    uint2 u = { pack_h2(a.x, a.y), pack_h2(a.z, a.w) };
    out[i] = u;
}

// ---------------------------------------------------------------------------
// Pre-pass 2: transpose + cvt all 4 weights: W[k][n] fp32 -> Wt[n][k] fp16.
// ---------------------------------------------------------------------------
__global__ __launch_bounds__(256)
void wT4_kernel(const float* __restrict__ wq, const float* __restrict__ wk,
                const float* __restrict__ wv, const float* __restrict__ wo,
                __half* __restrict__ twq, __half* __restrict__ twk,
                __half* __restrict__ twv, __half* __restrict__ two)
{
    __shared__ float ts[32][33];
    const float* W  = (blockIdx.z == 0) ? wq  : (blockIdx.z == 1) ? wk  :
                      (blockIdx.z == 2) ? wv  : wo;
    __half*      Wt = (blockIdx.z == 0) ? twq : (blockIdx.z == 1) ? twk :
                      (blockIdx.z == 2) ? twv : two;
    int k0 = blockIdx.x * 32, n0 = blockIdx.y * 32;
    int tx = threadIdx.x, ty = threadIdx.y;
    #pragma unroll
    for (int r = 0; r < 4; r++)
        ts[ty + r * 8][tx] = W[(size_t)(k0 + ty + r * 8) * 1024 + n0 + tx];
    __syncthreads();
    #pragma unroll
    for (int r = 0; r < 4; r++) {
        int n = ty + r * 8;
        Wt[(size_t)(n0 + n) * 1024 + k0 + tx] = __float2half_rn(ts[tx][n]);
    }
}

// ---------------------------------------------------------------------------
// FP16 GEMM with ldmatrix fragment loads. C = alpha*(A@W + bias).
// A fp16 natural [m][512u32]; Wt fp16 transposed [n][512u32].
// BM=BN=128, BK=64 halves (32 u32), 2-stage cp.async, 256 thr, warp 64x32,
// pitch 36. OUT: 0=fp32 natural, 1=fp16 natural, 2=fp16 V^T.
// ---------------------------------------------------------------------------
#define GP 36
#define GST (128 * GP)
#define GEMM_SMEM ((4 * GST) * 4)     // 73728 B

template<int OUT>
__global__ __launch_bounds__(256)
void gemm_f16(const uint32_t* __restrict__ A,
              const uint32_t* __restrict__ Wt,
              const float* __restrict__ bias,
              void* __restrict__ Cout,
              float alpha)
{
    extern __shared__ uint32_t sg[];
    uint32_t* Asm = sg;               // [2][128][GP]
    uint32_t* Bsm = sg + 2 * GST;     // [2][128][GP]

    const int tid  = threadIdx.x;
    const int lane = tid & 31;
    const int gid  = lane >> 2;
    const int tg   = lane & 3;
    const int wid  = tid >> 5;
    const int warp_m = wid & 1;
    const int warp_n = wid >> 1;
    const int m0 = blockIdx.y * 128;
    const int n0 = blockIdx.x * 128;

    const int aoff = ldsm_a_off(lane, GP);
    const int boff = ldsm_b_off(lane, GP);

    float c[4][4][4];
    #pragma unroll
    for (int mt = 0; mt < 4; mt++)
        #pragma unroll
        for (int nt = 0; nt < 4; nt++)
            #pragma unroll
            for (int i = 0; i < 4; i++) c[mt][nt][i] = 0.f;

    #pragma unroll
    for (int i = 0; i < 4; i++) {
        int idx = tid + i * 256;
        int row = idx >> 3, ch = (idx & 7) * 4;
        cpasync16(smem_u32(&Asm[row * GP + ch]), &A [(size_t)(m0 + row) * 512 + ch]);
        cpasync16(smem_u32(&Bsm[row * GP + ch]), &Wt[(size_t)(n0 + row) * 512 + ch]);
    }
    cpasync_commit();

    int st = 0;
    for (int k0 = 0; k0 < 512; k0 += 32) {
        cpasync_wait<0>();
        __syncthreads();

        if (k0 + 32 < 512) {
            uint32_t* Ad = Asm + (st ^ 1) * GST;
            uint32_t* Bd = Bsm + (st ^ 1) * GST;
            #pragma unroll
            for (int i = 0; i < 4; i++) {
                int idx = tid + i * 256;
                int row = idx >> 3, ch = (idx & 7) * 4;
                cpasync16(smem_u32(&Ad[row * GP + ch]),
                          &A [(size_t)(m0 + row) * 512 + k0 + 32 + ch]);
                cpasync16(smem_u32(&Bd[row * GP + ch]),
                          &Wt[(size_t)(n0 + row) * 512 + k0 + 32 + ch]);
            }
            cpasync_commit();
        }

        const uint32_t* As = Asm + st * GST;
        const uint32_t* Bs = Bsm + st * GST;

        #pragma unroll
        for (int ks = 0; ks < 4; ks++) {
            uint32_t af[4][4], bf[4][2];
            #pragma unroll
            for (int mt = 0; mt < 4; mt++) {
                int base = (warp_m * 64 + mt * 16) * GP + ks * 8 + aoff;
                ldsm_x4(af[mt][0], af[mt][1], af[mt][2], af[mt][3],
                        smem_u32(&As[base]));
            }
            #pragma unroll
            for (int ntp = 0; ntp < 2; ntp++) {
                int base = (warp_n * 32 + ntp * 16) * GP + ks * 8 + boff;
                ldsm_x4(bf[ntp * 2][0], bf[ntp * 2][1],
                        bf[ntp * 2 + 1][0], bf[ntp * 2 + 1][1],
                        smem_u32(&Bs[base]));
            }
            #pragma unroll
            for (int mt = 0; mt < 4; mt++)
                #pragma unroll
                for (int nt = 0; nt < 4; nt++)
                    mma_f16(c[mt][nt], af[mt][0], af[mt][1], af[mt][2], af[mt][3],
                            bf[nt][0], bf[nt][1]);
        }
        st ^= 1;
    }

    #pragma unroll
    for (int mt = 0; mt < 4; mt++) {
        int r0 = m0 + warp_m * 64 + mt * 16 + gid;
        #pragma unroll
        for (int nt = 0; nt < 4; nt++) {
            int col = n0 + warp_n * 32 + nt * 8 + tg * 2;
            float2 bb = *(const float2*)&bias[col];
            float v00 = alpha * (c[mt][nt][0] + bb.x);
            float v01 = alpha * (c[mt][nt][1] + bb.y);
            float v10 = alpha * (c[mt][nt][2] + bb.x);
            float v11 = alpha * (c[mt][nt][3] + bb.y);
            if (OUT == 0) {
                float* C = (float*)Cout;
                *(float2*)&C[(size_t)r0 * D_MODEL + col] = make_float2(v00, v01);
                *(float2*)&C[(size_t)(r0 + 8) * D_MODEL + col] = make_float2(v10, v11);
            } else if (OUT == 1) {
                uint32_t* C = (uint32_t*)Cout;
                C[(size_t)r0 * 512 + (col >> 1)]       = pack_h2(v00, v01);
                C[(size_t)(r0 + 8) * 512 + (col >> 1)] = pack_h2(v10, v11);
            } else {
                __half* VT = (__half*)Cout;
                int bi = r0 >> 11, tok = r0 & 2047;
                int h = col >> 6, d = col & 63;
                size_t row0 = ((size_t)(bi * 16 + h) * 64 + d) * 2048;
                size_t row1 = row0 + 2048;
                VT[row0 + tok]     = __float2half_rn(v00);
                VT[row1 + tok]     = __float2half_rn(v01);
                VT[row0 + tok + 8] = __float2half_rn(v10);
                VT[row1 + tok + 8] = __float2half_rn(v11);
            }
        }
    }
}

// ---------------------------------------------------------------------------
// FP16 flash attention with ldmatrix fragment loads (round-12 structure).
// smem = 55296 B.
// ---------------------------------------------------------------------------
#define AKP 36
#define AK_ST (64 * AKP)
#define AV_ST (64 * AKP)
#define AP_SZ (128 * AKP)
#define ATTN_SMEM ((2 * AK_ST + 2 * AV_ST + AP_SZ) * 4)

__global__ __launch_bounds__(256)
void attn_f16(const uint32_t* __restrict__ Q,
              const uint32_t* __restrict__ K,
              const uint32_t* __restrict__ V,
              uint32_t* __restrict__ O)
{
    extern __shared__ uint32_t sa[];
    uint32_t* Kbuf = sa;                        // [2][64][AKP]
    uint32_t* Vbuf = sa + 2 * AK_ST;            // [2][64][AKP]
    uint32_t* Ps   = sa + 2 * AK_ST + 2 * AV_ST; // [128][AKP]

    const int tid  = threadIdx.x;
    const int lane = tid & 31;
    const int wid  = tid >> 5;
    const int gid  = lane >> 2;
    const int tg   = lane & 3;
    const int rb   = wid * 16;

    const int q0 = blockIdx.x * 128;
    const int h  = blockIdx.y;
    const int b  = blockIdx.z;

    const int aoff = ldsm_a_off(lane, AKP);
    const int boff = ldsm_b_off(lane, AKP);

    const uint32_t* Qb  = Q + (size_t)b * SEQ * 512 + h * 32;
    const uint32_t* Kb  = K + (size_t)b * SEQ * 512 + h * 32;
    const uint32_t* Vtb = V + ((size_t)(b * 16 + h) * 64) * 1024;

    uint32_t qf[4][4];
    {
        const uint32_t* qr0 = Qb + (size_t)(q0 + rb + gid) * 512;
        const uint32_t* qr1 = qr0 + (size_t)8 * 512;
        #pragma unroll
        for (int ks = 0; ks < 4; ks++) {
            qf[ks][0] = qr0[ks * 8 + tg    ];
            qf[ks][1] = qr1[ks * 8 + tg    ];
            qf[ks][2] = qr0[ks * 8 + tg + 4];
            qf[ks][3] = qr1[ks * 8 + tg + 4];
        }
    }

    #pragma unroll
    for (int i = 0; i < 2; i++) {
        int idx = tid + i * 256;
        int r = idx >> 3, ch = (idx & 7) * 4;
        cpasync16(smem_u32(&Kbuf[r * AKP + ch]), &Kb[(size_t)r * 512 + ch]);
        cpasync16(smem_u32(&Vbuf[r * AKP + ch]), &Vtb[(size_t)r * 1024 + ch]);
    }
    cpasync_commit();

    float o[8][4];
    #pragma unroll
    for (int nt = 0; nt < 8; nt++)
        #pragma unroll
        for (int i = 0; i < 4; i++) o[nt][i] = 0.f;
    float m_i[2] = { -1e30f, -1e30f };
    float l_i[2] = { 0.f, 0.f };

    int st = 0;
    for (int kt = 0; kt < SEQ; kt += 64) {
        cpasync_wait<0>();
        __syncthreads();

        if (kt + 64 < SEQ) {
            uint32_t* Kd = Kbuf + (st ^ 1) * AK_ST;
            uint32_t* Vd = Vbuf + (st ^ 1) * AV_ST;
            #pragma unroll
            for (int i = 0; i < 2; i++) {
                int idx = tid + i * 256;
                int r = idx >> 3, ch = (idx & 7) * 4;
                cpasync16(smem_u32(&Kd[r * AKP + ch]),
                          &Kb[(size_t)(kt + 64 + r) * 512 + ch]);
                cpasync16(smem_u32(&Vd[r * AKP + ch]),
                          &Vtb[(size_t)r * 1024 + (kt + 64) / 2 + ch]);
            }
            cpasync_commit();
        }

        const uint32_t* Ks = Kbuf + st * AK_ST;
        const uint32_t* Vs = Vbuf + st * AV_ST;

        // S = Q @ K^T (K frags via ldmatrix: 4 nt-pairs per ks)
        float s[8][4];
        #pragma unroll
        for (int nt = 0; nt < 8; nt++)
            #pragma unroll
            for (int i = 0; i < 4; i++) s[nt][i] = 0.f;

        #pragma unroll
        for (int ks = 0; ks < 4; ks++) {
            uint32_t kf[8][2];
            #pragma unroll
            for (int ntp = 0; ntp < 4; ntp++) {
                int base = (ntp * 16) * AKP + ks * 8 + boff;
                ldsm_x4(kf[ntp * 2][0], kf[ntp * 2][1],
                        kf[ntp * 2 + 1][0], kf[ntp * 2 + 1][1],
                        smem_u32(&Ks[base]));
            }
            #pragma unroll
            for (int nt = 0; nt < 8; nt++)
                mma_f16(s[nt], qf[ks][0], qf[ks][1], qf[ks][2], qf[ks][3],
                        kf[nt][0], kf[nt][1]);
        }

        // Online softmax
        #pragma unroll
        for (int half = 0; half < 2; half++) {
            float mx = -1e30f;
            #pragma unroll
            for (int nt = 0; nt < 8; nt++)
                mx = fmaxf(mx, fmaxf(s[nt][half * 2], s[nt][half * 2 + 1]));
            mx = fmaxf(mx, __shfl_xor_sync(0xffffffffu, mx, 1));
            mx = fmaxf(mx, __shfl_xor_sync(0xffffffffu, mx, 2));

            float mnew = fmaxf(m_i[half], mx);
            float corr = __expf(m_i[half] - mnew);
            float rs = 0.f;
            #pragma unroll
            for (int nt = 0; nt < 8; nt++) {
                s[nt][half * 2]     = __expf(s[nt][half * 2]     - mnew);
                s[nt][half * 2 + 1] = __expf(s[nt][half * 2 + 1] - mnew);
                rs += s[nt][half * 2] + s[nt][half * 2 + 1];
            }
            rs += __shfl_xor_sync(0xffffffffu, rs, 1);
            rs += __shfl_xor_sync(0xffffffffu, rs, 2);

            l_i[half] = l_i[half] * corr + rs;
            m_i[half] = mnew;
            #pragma unroll
            for (int nt = 0; nt < 8; nt++) {
                o[nt][half * 2]     *= corr;
                o[nt][half * 2 + 1] *= corr;
            }
        }

        // P -> smem fp16 (warp-private rows)
        __syncwarp();
        #pragma unroll
        for (int nt = 0; nt < 8; nt++) {
            Ps[(rb + gid    ) * AKP + nt * 4 + tg] = pack_h2(s[nt][0], s[nt][1]);
            Ps[(rb + gid + 8) * AKP + nt * 4 + tg] = pack_h2(s[nt][2], s[nt][3]);
        }
        __syncwarp();

        // O += P @ V (P frags + V frags via ldmatrix)
        #pragma unroll
        for (int ks = 0; ks < 4; ks++) {
            uint32_t pf[4];
            ldsm_x4(pf[0], pf[1], pf[2], pf[3],
                    smem_u32(&Ps[rb * AKP + ks * 8 + aoff]));
            uint32_t vf[8][2];
            #pragma unroll
            for (int ntp = 0; ntp < 4; ntp++) {
                int base = (ntp * 16) * AKP + ks * 8 + boff;
                ldsm_x4(vf[ntp * 2][0], vf[ntp * 2][1],
                        vf[ntp * 2 + 1][0], vf[ntp * 2 + 1][1],
                        smem_u32(&Vs[base]));
            }
            #pragma unroll
            for (int nt = 0; nt < 8; nt++)
                mma_f16(o[nt], pf[0], pf[1], pf[2], pf[3], vf[nt][0], vf[nt][1]);
        }
        st ^= 1;
    }

    // Epilogue: normalize, write fp16 natural O
    float inv0 = 1.0f / l_i[0];
    float inv1 = 1.0f / l_i[1];
    uint32_t* Ob = O + (size_t)b * SEQ * 512 + h * 32;
    int r0 = q0 + rb + gid;
    #pragma unroll
    for (int nt = 0; nt < 8; nt++) {
        int u = nt * 4 + tg;
        Ob[(size_t)r0 * 512 + u]       = pack_h2(o[nt][0] * inv0, o[nt][1] * inv0);
        Ob[(size_t)(r0 + 8) * 512 + u] = pack_h2(o[nt][2] * inv1, o[nt][3] * inv1);
    }
}

// ---------------------------------------------------------------------------
// kernel_launch — inputs: q, k, v, w_q, b_q, w_k, b_k, w_v, b_v, w_o, b_o
// ---------------------------------------------------------------------------
extern "C" void kernel_launch(void* const* d_in, const int* in_sizes, int n_in,
                              void* d_out, int out_size)
{
    const float* q   = (const float*)d_in[0];
    const float* k   = (const float*)d_in[1];
    const float* v   = (const float*)d_in[2];
    const float* w_q = (const float*)d_in[3];
    const float* b_q = (const float*)d_in[4];
    const float* w_k = (const float*)d_in[5];
    const float* b_k = (const float*)d_in[6];
    const float* w_v = (const float*)d_in[7];
    const float* b_v = (const float*)d_in[8];
    const float* w_o = (const float*)d_in[9];
    const float* b_o = (const float*)d_in[10];
    float* out = (float*)d_out;

    uint32_t *tq, *tk, *tv, *twq, *twk, *twv, *two, *gq, *gk, *gv, *go;
    cudaGetSymbolAddress((void**)&tq,  t_q);
    cudaGetSymbolAddress((void**)&tk,  t_k);
    cudaGetSymbolAddress((void**)&tv,  t_v);
    cudaGetSymbolAddress((void**)&twq, t_wq);
    cudaGetSymbolAddress((void**)&twk, t_wk);
    cudaGetSymbolAddress((void**)&twv, t_wv);
    cudaGetSymbolAddress((void**)&two, t_wo);
    cudaGetSymbolAddress((void**)&gq,  g_Q);
    cudaGetSymbolAddress((void**)&gk,  g_K);
    cudaGetSymbolAddress((void**)&gv,  g_V);
    cudaGetSymbolAddress((void**)&go,  g_O);

    cudaFuncSetAttribute(gemm_f16<0>, cudaFuncAttributeMaxDynamicSharedMemorySize, GEMM_SMEM);
    cudaFuncSetAttribute(gemm_f16<1>, cudaFuncAttributeMaxDynamicSharedMemorySize, GEMM_SMEM);
    cudaFuncSetAttribute(gemm_f16<2>, cudaFuncAttributeMaxDynamicSharedMemorySize, GEMM_SMEM);
    cudaFuncSetAttribute(attn_f16,    cudaFuncAttributeMaxDynamicSharedMemorySize, ATTN_SMEM);

    const int n4_act = M_ROWS * D_MODEL / 4;
    dim3 act_grid(n4_act / 256, 3);
    cvt3_kernel<<<act_grid, 256>>>((const float4*)q, (const float4*)k, (const float4*)v,
                                   (uint2*)tq, (uint2*)tk, (uint2*)tv, n4_act);
    dim3 wt_grid(32, 32, 4), wt_block(32, 8);
    wT4_kernel<<<wt_grid, wt_block>>>(w_q, w_k, w_v, w_o,
                                      (__half*)twq, (__half*)twk, (__half*)twv, (__half*)two);

    dim3 gemm_grid(D_MODEL / 128, M_ROWS / 128);  // (8, 32)
    gemm_f16<1><<<gemm_grid, 256, GEMM_SMEM>>>(tq, twq, b_q, gq, 0.125f);
    gemm_f16<1><<<gemm_grid, 256, GEMM_SMEM>>>(tk, twk, b_k, gk, 1.0f);
    gemm_f16<2><<<gemm_grid, 256, GEMM_SMEM>>>(tv, twv, b_v, gv, 1.0f);

    dim3 attn_grid(SEQ / 128, N_HEADS, BATCH);    // (16, 16, 2)
    attn_f16<<<attn_grid, 256, ATTN_SMEM>>>(gq, gk, gv, go);

    gemm_f16<0><<<gemm_grid, 256, GEMM_SMEM>>>(go, two, b_o, out, 1.0f);
}

// round 14
// speedup vs baseline: 2.2583x; 1.0268x over previous
#include <cuda_runtime.h>
#include <cuda_fp16.h>
#include <cstdint>

#define D_MODEL 1024
#define N_HEADS 16
#define D_K     64
#define BATCH   2
#define SEQ     2048
#define M_ROWS  (BATCH * SEQ)   // 4096

// Scratch (allocation-free rule: __device__ globals).
__device__ uint32_t t_q [M_ROWS * D_MODEL / 2];   // fp16 natural acts [m][512 u32]
__device__ uint32_t t_k [M_ROWS * D_MODEL / 2];
__device__ uint32_t t_v [M_ROWS * D_MODEL / 2];
__device__ uint32_t t_wq[D_MODEL * D_MODEL / 2];  // fp16 TRANSPOSED weights Wt[n][512 u32]
__device__ uint32_t t_wk[D_MODEL * D_MODEL / 2];
__device__ uint32_t t_wv[D_MODEL * D_MODEL / 2];
__device__ uint32_t t_wo[D_MODEL * D_MODEL / 2];
__device__ uint32_t g_Q [M_ROWS * D_MODEL / 2];   // fp16 natural, pre-scaled
__device__ uint32_t g_K [M_ROWS * D_MODEL / 2];   // fp16 natural
__device__ uint32_t g_V [M_ROWS * D_MODEL / 2];   // fp16 V^T: [(b*16+h)*64+d][2048 halves]
__device__ uint32_t g_O [M_ROWS * D_MODEL / 2];   // fp16 natural (attn out)

__device__ __forceinline__ uint32_t pack_h2(float lo, float hi) {
    __half2 h = __floats2half2_rn(lo, hi);
    return *(uint32_t*)&h;
}

__device__ __forceinline__ void mma_f16(float c[4],
                                        uint32_t a0, uint32_t a1, uint32_t a2, uint32_t a3,
                                        uint32_t b0, uint32_t b1) {
    asm volatile(
        "mma.sync.aligned.m16n8k16.row.col.f32.f16.f16.f32 "
        "{%0,%1,%2,%3}, {%4,%5,%6,%7}, {%8,%9}, {%0,%1,%2,%3};"
        : "+f"(c[0]), "+f"(c[1]), "+f"(c[2]), "+f"(c[3])
        : "r"(a0), "r"(a1), "r"(a2), "r"(a3), "r"(b0), "r"(b1));
}

__device__ __forceinline__ void ldsm_x4(uint32_t& r0, uint32_t& r1,
                                        uint32_t& r2, uint32_t& r3, uint32_t addr) {
    asm volatile("ldmatrix.sync.aligned.m8n8.x4.shared.b16 {%0,%1,%2,%3}, [%4];"
                 : "=r"(r0), "=r"(r1), "=r"(r2), "=r"(r3) : "r"(addr));
}

__device__ __forceinline__ uint32_t smem_u32(const void* p) {
    return (uint32_t)__cvta_generic_to_shared(p);
}
__device__ __forceinline__ void cpasync16(uint32_t dst, const void* src) {
    asm volatile("cp.async.cg.shared.global [%0], [%1], 16;" :: "r"(dst), "l"(src));
}
__device__ __forceinline__ void cpasync_commit() {
    asm volatile("cp.async.commit_group;");
}
template<int N> __device__ __forceinline__ void cpasync_wait() {
    asm volatile("cp.async.wait_group %0;" :: "n"(N));
}

// ldmatrix per-lane offsets (u32 units) for pitch P
__device__ __forceinline__ int ldsm_a_off(int lane, int P) {
    return ((lane & 7) + ((lane >> 3) & 1) * 8) * P + (lane >> 4) * 4;
}
__device__ __forceinline__ int ldsm_b_off(int lane, int P) {
    return (lane & 7) * P + ((lane >> 3) & 1) * 4 + (lane >> 4) * 8 * P;
}

// ---------------------------------------------------------------------------
// Pre-pass 1: fp32 -> fp16 natural acts (fused q/k/v).
// ---------------------------------------------------------------------------
__global__ __launch_bounds__(256)
void cvt3_kernel(const float4* __restrict__ q, const float4* __restrict__ k,
                 const float4* __restrict__ v,
                 uint2* __restrict__ tq, uint2* __restrict__ tk,
                 uint2* __restrict__ tv, int n4)
{
    int i = blockIdx.x * 256 + threadIdx.x;
    if (i >= n4) return;
    const float4* in = (blockIdx.y == 0) ? q : (blockIdx.y == 1) ? k : v;
    uint2*       out = (blockIdx.y == 0) ? tq : (blockIdx.y == 1) ? tk : tv;
    float4 a = in[i];
    uint2 u = { pack_h2(a.x, a.y), pack_h2(a.z, a.w) };
    out[i] = u;
}

// ---------------------------------------------------------------------------
// Pre-pass 2: transpose + cvt all 4 weights: W[k][n] fp32 -> Wt[n][k] fp16.
// ---------------------------------------------------------------------------
__global__ __launch_bounds__(256)
void wT4_kernel(const float* __restrict__ wq, const float* __restrict__ wk,
                const float* __restrict__ wv, const float* __restrict__ wo,
                __half* __restrict__ twq, __half* __restrict__ twk,
                __half* __restrict__ twv, __half* __restrict__ two)
{
    __shared__ float ts[32][33];
    const float* W  = (blockIdx.z == 0) ? wq  : (blockIdx.z == 1) ? wk  :
                      (blockIdx.z == 2) ? wv  : wo;
    __half*      Wt = (blockIdx.z == 0) ? twq : (blockIdx.z == 1) ? twk :
                      (blockIdx.z == 2) ? twv : two;
    int k0 = blockIdx.x * 32, n0 = blockIdx.y * 32;
    int tx = threadIdx.x, ty = threadIdx.y;
    #pragma unroll
    for (int r = 0; r < 4; r++)
        ts[ty + r * 8][tx] = W[(size_t)(k0 + ty + r * 8) * 1024 + n0 + tx];
    __syncthreads();
    #pragma unroll
    for (int r = 0; r < 4; r++) {
        int n = ty + r * 8;
        Wt[(size_t)(n0 + n) * 1024 + k0 + tx] = __float2half_rn(ts[tx][n]);
    }
}

// ---------------------------------------------------------------------------
// GEMM core body (shared by fused-QKV and final kernels).
// A fp16 natural [m][512u32]; Wt fp16 transposed [n][512u32].
// BM=BN=128, BK=64 halves, 2-stage cp.async, 256 thr, warp 64x32, pitch 36.
// Fragment loads ldmatrix, software-pipelined (ks+1 prefetch).
// ---------------------------------------------------------------------------
#define GP 36
#define GST (128 * GP)
#define GEMM_SMEM ((4 * GST) * 4)     // 73728 B

struct GemmAcc { float c[4][4][4]; };

__device__ __forceinline__ void gemm_mainloop(
    const uint32_t* __restrict__ A, const uint32_t* __restrict__ Wt,
    uint32_t* sg, int m0, int n0, int tid, int lane, int wid, GemmAcc& acc)
{
    uint32_t* Asm = sg;
    uint32_t* Bsm = sg + 2 * GST;
    const int warp_m = wid & 1;
    const int warp_n = wid >> 1;
    const int aoff = ldsm_a_off(lane, GP);
    const int boff = ldsm_b_off(lane, GP);

    #pragma unroll
    for (int mt = 0; mt < 4; mt++)
        #pragma unroll
        for (int nt = 0; nt < 4; nt++)
            #pragma unroll
            for (int i = 0; i < 4; i++) acc.c[mt][nt][i] = 0.f;

    #pragma unroll
    for (int i = 0; i < 4; i++) {
        int idx = tid + i * 256;
        int row = idx >> 3, ch = (idx & 7) * 4;
        cpasync16(smem_u32(&Asm[row * GP + ch]), &A [(size_t)(m0 + row) * 512 + ch]);
        cpasync16(smem_u32(&Bsm[row * GP + ch]), &Wt[(size_t)(n0 + row) * 512 + ch]);
    }
    cpasync_commit();

    int st = 0;
    for (int k0 = 0; k0 < 512; k0 += 32) {
        cpasync_wait<0>();
        __syncthreads();

        if (k0 + 32 < 512) {
            uint32_t* Ad = Asm + (st ^ 1) * GST;
            uint32_t* Bd = Bsm + (st ^ 1) * GST;
            #pragma unroll
            for (int i = 0; i < 4; i++) {
                int idx = tid + i * 256;
                int row = idx >> 3, ch = (idx & 7) * 4;
                cpasync16(smem_u32(&Ad[row * GP + ch]),
                          &A [(size_t)(m0 + row) * 512 + k0 + 32 + ch]);
                cpasync16(smem_u32(&Bd[row * GP + ch]),
                          &Wt[(size_t)(n0 + row) * 512 + k0 + 32 + ch]);
            }
            cpasync_commit();
        }

        const uint32_t* As = Asm + st * GST;
        const uint32_t* Bs = Bsm + st * GST;

        uint32_t af[2][4][4], bf[2][4][2];
        // load ks=0 frags
        #pragma unroll
        for (int mt = 0; mt < 4; mt++)
            ldsm_x4(af[0][mt][0], af[0][mt][1], af[0][mt][2], af[0][mt][3],
                    smem_u32(&As[(warp_m * 64 + mt * 16) * GP + aoff]));
        #pragma unroll
        for (int ntp = 0; ntp < 2; ntp++)
            ldsm_x4(bf[0][ntp * 2][0], bf[0][ntp * 2][1],
                    bf[0][ntp * 2 + 1][0], bf[0][ntp * 2 + 1][1],
                    smem_u32(&Bs[(warp_n * 32 + ntp * 16) * GP + boff]));

        #pragma unroll
        for (int ks = 0; ks < 4; ks++) {
            int cur = ks & 1, nxt = cur ^ 1;
            if (ks < 3) {   // prefetch ks+1 frags before consuming ks
                #pragma unroll
                for (int mt = 0; mt < 4; mt++)
                    ldsm_x4(af[nxt][mt][0], af[nxt][mt][1], af[nxt][mt][2], af[nxt][mt][3],
                            smem_u32(&As[(warp_m * 64 + mt * 16) * GP + (ks + 1) * 8 + aoff]));
                #pragma unroll
                for (int ntp = 0; ntp < 2; ntp++)
                    ldsm_x4(bf[nxt][ntp * 2][0], bf[nxt][ntp * 2][1],
                            bf[nxt][ntp * 2 + 1][0], bf[nxt][ntp * 2 + 1][1],
                            smem_u32(&Bs[(warp_n * 32 + ntp * 16) * GP + (ks + 1) * 8 + boff]));
            }
            #pragma unroll
            for (int mt = 0; mt < 4; mt++)
                #pragma unroll
                for (int nt = 0; nt < 4; nt++)
                    mma_f16(acc.c[mt][nt],
                            af[cur][mt][0], af[cur][mt][1], af[cur][mt][2], af[cur][mt][3],
                            bf[cur][nt][0], bf[cur][nt][1]);
        }
        st ^= 1;
    }
}

// Fused QKV projection: blockIdx.z selects {A, W, bias, C, alpha, epilogue}.
__global__ __launch_bounds__(256)
void gemm_qkv(const float* __restrict__ b_q, const float* __restrict__ b_k,
              const float* __restrict__ b_v)
{
    extern __shared__ uint32_t sg[];
    const int tid  = threadIdx.x;
    const int lane = tid & 31;
    const int wid  = tid >> 5;
    const int gid  = lane >> 2;
    const int tg   = lane & 3;
    const int m0 = blockIdx.y * 128;
    const int n0 = blockIdx.x * 128;
    const int z  = blockIdx.z;

    const uint32_t* A  = (z == 0) ? t_q  : (z == 1) ? t_k  : t_v;
    const uint32_t* Wt = (z == 0) ? t_wq : (z == 1) ? t_wk : t_wv;
    const float*  bias = (z == 0) ? b_q  : (z == 1) ? b_k  : b_v;
    const float  alpha = (z == 0) ? 0.125f : 1.0f;

    GemmAcc acc;
    gemm_mainloop(A, Wt, sg, m0, n0, tid, lane, wid, acc);

    const int warp_m = wid & 1;
    const int warp_n = wid >> 1;
    #pragma unroll
    for (int mt = 0; mt < 4; mt++) {
        int r0 = m0 + warp_m * 64 + mt * 16 + gid;
        #pragma unroll
        for (int nt = 0; nt < 4; nt++) {
            int col = n0 + warp_n * 32 + nt * 8 + tg * 2;
            float2 bb = *(const float2*)&bias[col];
            float v00 = alpha * (acc.c[mt][nt][0] + bb.x);
            float v01 = alpha * (acc.c[mt][nt][1] + bb.y);
            float v10 = alpha * (acc.c[mt][nt][2] + bb.x);
            float v11 = alpha * (acc.c[mt][nt][3] + bb.y);
            if (z < 2) {
                uint32_t* C = (z == 0) ? g_Q : g_K;
                C[(size_t)r0 * 512 + (col >> 1)]       = pack_h2(v00, v01);
                C[(size_t)(r0 + 8) * 512 + (col >> 1)] = pack_h2(v10, v11);
            } else {
                __half* VT = (__half*)g_V;
                int bi = r0 >> 11, tok = r0 & 2047;
                int h = col >> 6, d = col & 63;
                size_t row0 = ((size_t)(bi * 16 + h) * 64 + d) * 2048;
                size_t row1 = row0 + 2048;
                VT[row0 + tok]     = __float2half_rn(v00);
                VT[row1 + tok]     = __float2half_rn(v01);
                VT[row0 + tok + 8] = __float2half_rn(v10);
                VT[row1 + tok + 8] = __float2half_rn(v11);
            }
        }
    }
}

// Final output projection: fp32 natural out.
__global__ __launch_bounds__(256)
void gemm_out(const float* __restrict__ bias, float* __restrict__ Cout)
{
    extern __shared__ uint32_t sg[];
    const int tid  = threadIdx.x;
    const int lane = tid & 31;
    const int wid  = tid >> 5;
    const int gid  = lane >> 2;
    const int tg   = lane & 3;
    const int m0 = blockIdx.y * 128;
    const int n0 = blockIdx.x * 128;

    GemmAcc acc;
    gemm_mainloop(g_O, t_wo, sg, m0, n0, tid, lane, wid, acc);

    const int warp_m = wid & 1;
    const int warp_n = wid >> 1;
    #pragma unroll
    for (int mt = 0; mt < 4; mt++) {
        int r0 = m0 + warp_m * 64 + mt * 16 + gid;
        #pragma unroll
        for (int nt = 0; nt < 4; nt++) {
            int col = n0 + warp_n * 32 + nt * 8 + tg * 2;
            float2 bb = *(const float2*)&bias[col];
            *(float2*)&Cout[(size_t)r0 * D_MODEL + col] =
                make_float2(acc.c[mt][nt][0] + bb.x, acc.c[mt][nt][1] + bb.y);
            *(float2*)&Cout[(size_t)(r0 + 8) * D_MODEL + col] =
                make_float2(acc.c[mt][nt][2] + bb.x, acc.c[mt][nt][3] + bb.y);
        }
    }
}

// ---------------------------------------------------------------------------
// FP16 flash attention with ldmatrix fragment loads — round-13 passing version.
// smem = 55296 B.
// ---------------------------------------------------------------------------
#define AKP 36
#define AK_ST (64 * AKP)
#define AV_ST (64 * AKP)
#define AP_SZ (128 * AKP)
#define ATTN_SMEM ((2 * AK_ST + 2 * AV_ST + AP_SZ) * 4)

__global__ __launch_bounds__(256)
void attn_f16(const uint32_t* __restrict__ Q,
              const uint32_t* __restrict__ K,
              const uint32_t* __restrict__ V,
              uint32_t* __restrict__ O)
{
    extern __shared__ uint32_t sa[];
    uint32_t* Kbuf = sa;
    uint32_t* Vbuf = sa + 2 * AK_ST;
    uint32_t* Ps   = sa + 2 * AK_ST + 2 * AV_ST;

    const int tid  = threadIdx.x;
    const int lane = tid & 31;
    const int wid  = tid >> 5;
    const int gid  = lane >> 2;
    const int tg   = lane & 3;
    const int rb   = wid * 16;

    const int q0 = blockIdx.x * 128;
    const int h  = blockIdx.y;
    const int b  = blockIdx.z;

    const int aoff = ldsm_a_off(lane, AKP);
    const int boff = ldsm_b_off(lane, AKP);

    const uint32_t* Qb  = Q + (size_t)b * SEQ * 512 + h * 32;
    const uint32_t* Kb  = K + (size_t)b * SEQ * 512 + h * 32;
    const uint32_t* Vtb = V + ((size_t)(b * 16 + h) * 64) * 1024;

    uint32_t qf[4][4];
    {
        const uint32_t* qr0 = Qb + (size_t)(q0 + rb + gid) * 512;
        const uint32_t* qr1 = qr0 + (size_t)8 * 512;
        #pragma unroll
        for (int ks = 0; ks < 4; ks++) {
            qf[ks][0] = qr0[ks * 8 + tg    ];
            qf[ks][1] = qr1[ks * 8 + tg    ];
            qf[ks][2] = qr0[ks * 8 + tg + 4];
            qf[ks][3] = qr1[ks * 8 + tg + 4];
        }
    }

    #pragma unroll
    for (int i = 0; i < 2; i++) {
        int idx = tid + i * 256;
        int r = idx >> 3, ch = (idx & 7) * 4;
        cpasync16(smem_u32(&Kbuf[r * AKP + ch]), &Kb[(size_t)r * 512 + ch]);
        cpasync16(smem_u32(&Vbuf[r * AKP + ch]), &Vtb[(size_t)r * 1024 + ch]);
    }
    cpasync_commit();

    float o[8][4];
    #pragma unroll
    for (int nt = 0; nt < 8; nt++)
        #pragma unroll
        for (int i = 0; i < 4; i++) o[nt][i] = 0.f;
    float m_i[2] = { -1e30f, -1e30f };
    float l_i[2] = { 0.f, 0.f };

    int st = 0;
    for (int kt = 0; kt < SEQ; kt += 64) {
        cpasync_wait<0>();
        __syncthreads();

        if (kt + 64 < SEQ) {
            uint32_t* Kd = Kbuf + (st ^ 1) * AK_ST;
            uint32_t* Vd = Vbuf + (st ^ 1) * AV_ST;
            #pragma unroll
            for (int i = 0; i < 2; i++) {
                int idx = tid + i * 256;
                int r = idx >> 3, ch = (idx & 7) * 4;
                cpasync16(smem_u32(&Kd[r * AKP + ch]),
                          &Kb[(size_t)(kt + 64 + r) * 512 + ch]);
                cpasync16(smem_u32(&Vd[r * AKP + ch]),
                          &Vtb[(size_t)r * 1024 + (kt + 64) / 2 + ch]);
            }
            cpasync_commit();
        }

        const uint32_t* Ks = Kbuf + st * AK_ST;
        const uint32_t* Vs = Vbuf + st * AV_ST;

        float s[8][4];
        #pragma unroll
        for (int nt = 0; nt < 8; nt++)
            #pragma unroll
            for (int i = 0; i < 4; i++) s[nt][i] = 0.f;

        #pragma unroll
        for (int ks = 0; ks < 4; ks++) {
            uint32_t kf[8][2];
            #pragma unroll
            for (int ntp = 0; ntp < 4; ntp++) {
                int base = (ntp * 16) * AKP + ks * 8 + boff;
                ldsm_x4(kf[ntp * 2][0], kf[ntp * 2][1],
                        kf[ntp * 2 + 1][0], kf[ntp * 2 + 1][1],
                        smem_u32(&Ks[base]));
            }
            #pragma unroll
            for (int nt = 0; nt < 8; nt++)
                mma_f16(s[nt], qf[ks][0], qf[ks][1], qf[ks][2], qf[ks][3],
                        kf[nt][0], kf[nt][1]);
        }

        #pragma unroll
        for (int half = 0; half < 2; half++) {
            float mx = -1e30f;
            #pragma unroll
            for (int nt = 0; nt < 8; nt++)
                mx = fmaxf(mx, fmaxf(s[nt][half * 2], s[nt][half * 2 + 1]));
            mx = fmaxf(mx, __shfl_xor_sync(0xffffffffu, mx, 1));
            mx = fmaxf(mx, __shfl_xor_sync(0xffffffffu, mx, 2));

            float mnew = fmaxf(m_i[half], mx);
            float corr = __expf(m_i[half] - mnew);
            float rs = 0.f;
            #pragma unroll
            for (int nt = 0; nt < 8; nt++) {
                s[nt][half * 2]     = __expf(s[nt][half * 2]     - mnew);
                s[nt][half * 2 + 1] = __expf(s[nt][half * 2 + 1] - mnew);
                rs += s[nt][half * 2] + s[nt][half * 2 + 1];
            }
            rs += __shfl_xor_sync(0xffffffffu, rs, 1);
            rs += __shfl_xor_sync(0xffffffffu, rs, 2);

            l_i[half] = l_i[half] * corr + rs;
            m_i[half] = mnew;
            #pragma unroll
            for (int nt = 0; nt < 8; nt++) {
                o[nt][half * 2]     *= corr;
                o[nt][half * 2 + 1] *= corr;
            }
        }

        __syncwarp();
        #pragma unroll
        for (int nt = 0; nt < 8; nt++) {
            Ps[(rb + gid    ) * AKP + nt * 4 + tg] = pack_h2(s[nt][0], s[nt][1]);
            Ps[(rb + gid + 8) * AKP + nt * 4 + tg] = pack_h2(s[nt][2], s[nt][3]);
        }
        __syncwarp();

        #pragma unroll
        for (int ks = 0; ks < 4; ks++) {
            uint32_t pf[4];
            ldsm_x4(pf[0], pf[1], pf[2], pf[3],
                    smem_u32(&Ps[rb * AKP + ks * 8 + aoff]));
            uint32_t vf[8][2];
            #pragma unroll
            for (int ntp = 0; ntp < 4; ntp++) {
                int base = (ntp * 16) * AKP + ks * 8 + boff;
                ldsm_x4(vf[ntp * 2][0], vf[ntp * 2][1],
                        vf[ntp * 2 + 1][0], vf[ntp * 2 + 1][1],
                        smem_u32(&Vs[base]));
            }
            #pragma unroll
            for (int nt = 0; nt < 8; nt++)
                mma_f16(o[nt], pf[0], pf[1], pf[2], pf[3], vf[nt][0], vf[nt][1]);
        }
        st ^= 1;
    }

    float inv0 = 1.0f / l_i[0];
    float inv1 = 1.0f / l_i[1];
    uint32_t* Ob = O + (size_t)b * SEQ * 512 + h * 32;
    int r0 = q0 + rb + gid;
    #pragma unroll
    for (int nt = 0; nt < 8; nt++) {
        int u = nt * 4 + tg;
        Ob[(size_t)r0 * 512 + u]       = pack_h2(o[nt][0] * inv0, o[nt][1] * inv0);
        Ob[(size_t)(r0 + 8) * 512 + u] = pack_h2(o[nt][2] * inv1, o[nt][3] * inv1);
    }
}

// ---------------------------------------------------------------------------
// kernel_launch — inputs: q, k, v, w_q, b_q, w_k, b_k, w_v, b_v, w_o, b_o
// ---------------------------------------------------------------------------
extern "C" void kernel_launch(void* const* d_in, const int* in_sizes, int n_in,
                              void* d_out, int out_size)
{
    const float* q   = (const float*)d_in[0];
    const float* k   = (const float*)d_in[1];
    const float* v   = (const float*)d_in[2];
    const float* w_q = (const float*)d_in[3];
    const float* b_q = (const float*)d_in[4];
    const float* w_k = (const float*)d_in[5];
    const float* b_k = (const float*)d_in[6];
    const float* w_v = (const float*)d_in[7];
    const float* b_v = (const float*)d_in[8];
    const float* w_o = (const float*)d_in[9];
    const float* b_o = (const float*)d_in[10];
    float* out = (float*)d_out;

    uint32_t *tq, *tk, *tv, *twq, *twk, *twv, *two, *gq, *gk, *gv, *go;
    cudaGetSymbolAddress((void**)&tq,  t_q);
    cudaGetSymbolAddress((void**)&tk,  t_k);
    cudaGetSymbolAddress((void**)&tv,  t_v);
    cudaGetSymbolAddress((void**)&twq, t_wq);
    cudaGetSymbolAddress((void**)&twk, t_wk);
    cudaGetSymbolAddress((void**)&twv, t_wv);
    cudaGetSymbolAddress((void**)&two, t_wo);
    cudaGetSymbolAddress((void**)&gq,  g_Q);
    cudaGetSymbolAddress((void**)&gk,  g_K);
    cudaGetSymbolAddress((void**)&gv,  g_V);
    cudaGetSymbolAddress((void**)&go,  g_O);

    cudaFuncSetAttribute(gemm_qkv, cudaFuncAttributeMaxDynamicSharedMemorySize, GEMM_SMEM);
    cudaFuncSetAttribute(gemm_out, cudaFuncAttributeMaxDynamicSharedMemorySize, GEMM_SMEM);
    cudaFuncSetAttribute(attn_f16, cudaFuncAttributeMaxDynamicSharedMemorySize, ATTN_SMEM);

    const int n4_act = M_ROWS * D_MODEL / 4;
    dim3 act_grid(n4_act / 256, 3);
    cvt3_kernel<<<act_grid, 256>>>((const float4*)q, (const float4*)k, (const float4*)v,
                                   (uint2*)tq, (uint2*)tk, (uint2*)tv, n4_act);
    dim3 wt_grid(32, 32, 4), wt_block(32, 8);
    wT4_kernel<<<wt_grid, wt_block>>>(w_q, w_k, w_v, w_o,
                                      (__half*)twq, (__half*)twk, (__half*)twv, (__half*)two);

    dim3 qkv_grid(D_MODEL / 128, M_ROWS / 128, 3);   // (8, 32, 3) = 768 CTAs
    gemm_qkv<<<qkv_grid, 256, GEMM_SMEM>>>(b_q, b_k, b_v);

    dim3 attn_grid(SEQ / 128, N_HEADS, BATCH);       // (16, 16, 2)
    attn_f16<<<attn_grid, 256, ATTN_SMEM>>>(gq, gk, gv, go);

    dim3 out_grid(D_MODEL / 128, M_ROWS / 128);      // (8, 32)
    gemm_out<<<out_grid, 256, GEMM_SMEM>>>(b_o, out);
}